// round 3
// baseline (speedup 1.0000x reference)
#include <cuda_runtime.h>

// Problem constants
#define CB   4
#define CS   2048
#define CH   1024
#define CNH  16
#define CHD  64
#define CWIN 256

// Scratch (allocation-free rule: __device__ globals)
__device__ float g_Q[CB * CS * CH];
__device__ float g_K[CB * CS * CH];
__device__ float g_V[CB * CS * CH];
__device__ float g_ctx[CB * CS * CH];

// ---------------------------------------------------------------------------
// SGEMM: C[M,N] = A[M,K] * W[N,K]^T   (torch Linear layout: W is [out,in])
// MASKED variant: A element-wise multiplied by Msk, bias added to output.
// Tiles: 64x64x16, 256 threads, 4x4 micro-tile per thread.
// ---------------------------------------------------------------------------
template <bool MASKED>
__global__ void __launch_bounds__(256) sgemm_nt(
    const float* __restrict__ A, const float* __restrict__ Wt,
    const float* __restrict__ Msk, const float* __restrict__ bias,
    float* __restrict__ C, int M, int N, int K)
{
    __shared__ float As[16][68];  // [k][m], stride 68 floats = 272B (16B aligned)
    __shared__ float Bs[16][68];  // [k][n]

    const int tid = threadIdx.x;
    const int m0  = blockIdx.y * 64;
    const int n0  = blockIdx.x * 64;
    const int lr  = tid >> 2;        // 0..63 row within tile
    const int lc  = (tid & 3) * 4;   // 0,4,8,12 k-offset
    const int tx  = tid & 15;
    const int ty  = tid >> 4;

    float acc[4][4] = {};

    const float* Arow = A  + (size_t)(m0 + lr) * K + lc;
    const float* Wrow = Wt + (size_t)(n0 + lr) * K + lc;
    const float* Mrow = MASKED ? (Msk + (size_t)(m0 + lr) * K + lc) : nullptr;

    for (int k0 = 0; k0 < K; k0 += 16) {
        float4 a4 = *(const float4*)(Arow + k0);
        float4 b4 = *(const float4*)(Wrow + k0);
        if (MASKED) {
            float4 m4 = *(const float4*)(Mrow + k0);
            a4.x *= m4.x; a4.y *= m4.y; a4.z *= m4.z; a4.w *= m4.w;
        }
        __syncthreads();  // previous iteration's smem reads complete
        As[lc + 0][lr] = a4.x; As[lc + 1][lr] = a4.y;
        As[lc + 2][lr] = a4.z; As[lc + 3][lr] = a4.w;
        Bs[lc + 0][lr] = b4.x; Bs[lc + 1][lr] = b4.y;
        Bs[lc + 2][lr] = b4.z; Bs[lc + 3][lr] = b4.w;
        __syncthreads();

#pragma unroll
        for (int kk = 0; kk < 16; kk++) {
            float4 av = *(const float4*)&As[kk][ty * 4];
            float4 bv = *(const float4*)&Bs[kk][tx * 4];
            float a_[4] = {av.x, av.y, av.z, av.w};
            float b_[4] = {bv.x, bv.y, bv.z, bv.w};
#pragma unroll
            for (int i = 0; i < 4; i++)
#pragma unroll
                for (int j = 0; j < 4; j++)
                    acc[i][j] = fmaf(a_[i], b_[j], acc[i][j]);
        }
    }

#pragma unroll
    for (int i = 0; i < 4; i++) {
        int row = m0 + ty * 4 + i;
        float4 o;
        o.x = acc[i][0]; o.y = acc[i][1]; o.z = acc[i][2]; o.w = acc[i][3];
        if (MASKED) {
            int nb = n0 + tx * 4;
            o.x += bias[nb + 0]; o.y += bias[nb + 1];
            o.z += bias[nb + 2]; o.w += bias[nb + 3];
        }
        *(float4*)(C + (size_t)row * N + n0 + tx * 4) = o;
    }
}

// ---------------------------------------------------------------------------
// Local windowed attention, one CTA per (64-query tile, head, batch).
// Keys span [qbase-256, qbase+63] = 5 key blocks of 64.
// Two-pass exact softmax over scores materialized in smem (no 1/sqrt(d) scale,
// matching the reference). Output written to g_ctx in merged-head layout.
// ---------------------------------------------------------------------------
struct AttnSmem {
    float Qs[64][68];    // [d][q]
    float KVs[64][68];   // K pass: [d][t]; V pass: [t][d]
    float Ss[320][68];   // [t][q] scores, then P
    float pmax[4][64];
    float psum[4][64];
    float rowmax[64];
    float rowsum[64];
};

extern __shared__ char attn_smem_raw[];

__global__ void __launch_bounds__(256) local_attn_kernel()
{
    AttnSmem& sm = *reinterpret_cast<AttnSmem*>(attn_smem_raw);
    const int tid   = threadIdx.x;
    const int qbase = blockIdx.x * 64;
    const int head  = blockIdx.y;
    const int b     = blockIdx.z;
    const int tx    = tid & 15;
    const int ty    = tid >> 4;
    const size_t base = ((size_t)b * CS) * CH + (size_t)head * CHD;

    // Load Q tile transposed: Qs[d][q]
#pragma unroll
    for (int it = 0; it < 4; it++) {
        int idx = tid + it * 256;
        int row = idx >> 4;
        int d   = (idx & 15) * 4;
        float4 v = *(const float4*)(g_Q + base + (size_t)(qbase + row) * CH + d);
        sm.Qs[d + 0][row] = v.x; sm.Qs[d + 1][row] = v.y;
        sm.Qs[d + 2][row] = v.z; sm.Qs[d + 3][row] = v.w;
    }

    // ---- Pass A: scores for 5 key blocks into Ss[t][q] ----
    for (int kb = 0; kb < 5; kb++) {
        int kbase = qbase - CWIN + kb * 64;
        __syncthreads();  // prior compute done with KVs / Q stores visible
        if (kbase + 63 < 0) {
            // entire block below j=0: fully masked
            for (int idx = tid; idx < 64 * 64; idx += 256)
                sm.Ss[kb * 64 + (idx >> 6)][idx & 63] = -1e30f;
            continue;
        }
        // Load K block transposed: KVs[d][t]
#pragma unroll
        for (int it = 0; it < 4; it++) {
            int idx = tid + it * 256;
            int t   = idx >> 4;
            int d   = (idx & 15) * 4;
            int j   = kbase + t;
            float4 v = make_float4(0.f, 0.f, 0.f, 0.f);
            if (j >= 0)
                v = *(const float4*)(g_K + base + (size_t)j * CH + d);
            sm.KVs[d + 0][t] = v.x; sm.KVs[d + 1][t] = v.y;
            sm.KVs[d + 2][t] = v.z; sm.KVs[d + 3][t] = v.w;
        }
        __syncthreads();

        float s[4][4] = {};
#pragma unroll 16
        for (int kk = 0; kk < 64; kk++) {
            float4 av = *(const float4*)&sm.Qs[kk][ty * 4];
            float4 bv = *(const float4*)&sm.KVs[kk][tx * 4];
            float a_[4] = {av.x, av.y, av.z, av.w};
            float b_[4] = {bv.x, bv.y, bv.z, bv.w};
#pragma unroll
            for (int i = 0; i < 4; i++)
#pragma unroll
                for (int j = 0; j < 4; j++)
                    s[i][j] = fmaf(a_[i], b_[j], s[i][j]);
        }
        // Mask and store: valid iff 0 <= j <= i and j > i - WIN
#pragma unroll
        for (int i = 0; i < 4; i++) {
            int gi = qbase + ty * 4 + i;
#pragma unroll
            for (int j = 0; j < 4; j++) {
                int t  = tx * 4 + j;
                int gj = kbase + t;
                bool ok = (gj >= 0) && (gj <= gi) && (gj > gi - CWIN);
                sm.Ss[kb * 64 + t][ty * 4 + i] = ok ? s[i][j] : -1e30f;
            }
        }
    }
    __syncthreads();

    // ---- Softmax (exact, two-pass). thread -> (q = tid&63, part p = tid>>6, 80 t's each)
    const int q = tid & 63;
    const int p = tid >> 6;
    {
        float mx = -1e30f;
        for (int t = p * 80; t < p * 80 + 80; t++)
            mx = fmaxf(mx, sm.Ss[t][q]);
        sm.pmax[p][q] = mx;
    }
    __syncthreads();
    if (tid < 64) {
        sm.rowmax[tid] = fmaxf(fmaxf(sm.pmax[0][tid], sm.pmax[1][tid]),
                               fmaxf(sm.pmax[2][tid], sm.pmax[3][tid]));
    }
    __syncthreads();
    {
        float rm = sm.rowmax[q];
        float sum = 0.f;
        for (int t = p * 80; t < p * 80 + 80; t++) {
            float e = __expf(sm.Ss[t][q] - rm);
            sm.Ss[t][q] = e;
            sum += e;
        }
        sm.psum[p][q] = sum;
    }
    __syncthreads();
    if (tid < 64) {
        sm.rowsum[tid] = sm.psum[0][tid] + sm.psum[1][tid] +
                         sm.psum[2][tid] + sm.psum[3][tid];
    }

    // ---- Pass C: O = P * V, streaming V blocks through KVs[t][d] ----
    float o[4][4] = {};
    for (int kb = 0; kb < 5; kb++) {
        int kbase = qbase - CWIN + kb * 64;
        if (kbase + 63 < 0) continue;  // uniform branch; P there is exactly 0
        __syncthreads();  // also makes rowsum + P visible before first use
#pragma unroll
        for (int it = 0; it < 4; it++) {
            int idx = tid + it * 256;
            int t   = idx >> 4;
            int d   = (idx & 15) * 4;
            int j   = kbase + t;
            float4 v = make_float4(0.f, 0.f, 0.f, 0.f);
            if (j >= 0)
                v = *(const float4*)(g_V + base + (size_t)j * CH + d);
            *(float4*)&sm.KVs[t][d] = v;
        }
        __syncthreads();
#pragma unroll 16
        for (int kk = 0; kk < 64; kk++) {
            float4 av = *(const float4*)&sm.Ss[kb * 64 + kk][ty * 4];
            float4 bv = *(const float4*)&sm.KVs[kk][tx * 4];
            float a_[4] = {av.x, av.y, av.z, av.w};
            float b_[4] = {bv.x, bv.y, bv.z, bv.w};
#pragma unroll
            for (int i = 0; i < 4; i++)
#pragma unroll
                for (int j = 0; j < 4; j++)
                    o[i][j] = fmaf(a_[i], b_[j], o[i][j]);
        }
    }

    // Normalize and write context (merged-head layout)
#pragma unroll
    for (int i = 0; i < 4; i++) {
        float inv = 1.0f / sm.rowsum[ty * 4 + i];
        float4 v;
        v.x = o[i][0] * inv; v.y = o[i][1] * inv;
        v.z = o[i][2] * inv; v.w = o[i][3] * inv;
        *(float4*)(g_ctx + base + (size_t)(qbase + ty * 4 + i) * CH + tx * 4) = v;
    }
}

// ---------------------------------------------------------------------------
// kernel_launch: 3 projection GEMMs -> local attention -> masked output GEMM
// ---------------------------------------------------------------------------
extern "C" void kernel_launch(void* const* d_in, const int* in_sizes, int n_in,
                              void* d_out, int out_size)
{
    const float* x   = (const float*)d_in[0];
    const float* xc  = (const float*)d_in[1];
    const float* abl = (const float*)d_in[2];
    const float* Wq  = (const float*)d_in[3];
    const float* Wk  = (const float*)d_in[4];
    const float* Wv  = (const float*)d_in[5];
    const float* Wo  = (const float*)d_in[6];
    const float* bo  = (const float*)d_in[7];
    float* out = (float*)d_out;

    float *qp, *kp, *vp, *cp;
    cudaGetSymbolAddress((void**)&qp, g_Q);
    cudaGetSymbolAddress((void**)&kp, g_K);
    cudaGetSymbolAddress((void**)&vp, g_V);
    cudaGetSymbolAddress((void**)&cp, g_ctx);

    const int M = CB * CS;               // 8192
    dim3 ggrid(CH / 64, M / 64);         // (16, 128)

    sgemm_nt<false><<<ggrid, 256>>>(x,  Wq, nullptr, nullptr, qp, M, CH, CH);
    sgemm_nt<false><<<ggrid, 256>>>(xc, Wk, nullptr, nullptr, kp, M, CH, CH);
    sgemm_nt<false><<<ggrid, 256>>>(xc, Wv, nullptr, nullptr, vp, M, CH, CH);

    cudaFuncSetAttribute(local_attn_kernel,
                         cudaFuncAttributeMaxDynamicSharedMemorySize,
                         (int)sizeof(AttnSmem));
    local_attn_kernel<<<dim3(CS / 64, CNH, CB), 256, sizeof(AttnSmem)>>>();

    sgemm_nt<true><<<ggrid, 256>>>(cp, Wo, abl, bo, out, M, CH, CH);
}

// round 6
// speedup vs baseline: 2.3123x; 2.3123x over previous
#include <cuda_runtime.h>
#include <cuda_bf16.h>
#include <cstdint>

// Problem constants
#define CB   4
#define CS   2048
#define CH   1024
#define CNH  16
#define CHD  64
#define CWIN 256

#define GM   (CB * CS)   // 8192
#define GN   CH          // 1024
#define GK   CH          // 1024
#define KP   (3 * GK)    // 3072 concatenated-K for bf16x3

// ---------------------------------------------------------------------------
// Scratch (allocation-free rule: __device__ globals)
// ---------------------------------------------------------------------------
__device__ float g_Q[GM * CH];
__device__ float g_K[GM * CH];
__device__ float g_V[GM * CH];
__device__ float g_ctx[GM * CH];

// Concatenated-K bf16 operands: A' = [hi | hi | lo], B' = [hi | lo | hi]
__device__ __nv_bfloat16 g_Ax[GM * KP];    // from x
__device__ __nv_bfloat16 g_Axc[GM * KP];   // from x_clean
__device__ __nv_bfloat16 g_Ac[GM * KP];    // from ctx * ablation_mask
__device__ __nv_bfloat16 g_Bq[GN * KP];
__device__ __nv_bfloat16 g_Bk[GN * KP];
__device__ __nv_bfloat16 g_Bv[GN * KP];
__device__ __nv_bfloat16 g_Bo[GN * KP];

extern __shared__ char dsmem[];

// ---------------------------------------------------------------------------
// Helpers
// ---------------------------------------------------------------------------
__device__ __forceinline__ uint32_t smem_u32(const void* p) {
    uint32_t a;
    asm("{ .reg .u64 t; cvta.to.shared.u64 t, %1; cvt.u32.u64 %0, t; }"
        : "=r"(a) : "l"(p));
    return a;
}

__device__ __forceinline__ void cp16(uint32_t dst, const void* src) {
    asm volatile("cp.async.cg.shared.global [%0], [%1], 16;" :: "r"(dst), "l"(src) : "memory");
}
#define CP_COMMIT() asm volatile("cp.async.commit_group;" ::: "memory")

__device__ __forceinline__ void ldsm4(uint32_t* r, uint32_t addr) {
    asm volatile("ldmatrix.sync.aligned.m8n8.x4.shared.b16 {%0,%1,%2,%3}, [%4];"
                 : "=r"(r[0]), "=r"(r[1]), "=r"(r[2]), "=r"(r[3]) : "r"(addr));
}

__device__ __forceinline__ void mma16816(float* c, const uint32_t* a, const uint32_t* b) {
    asm volatile(
        "mma.sync.aligned.m16n8k16.row.col.f32.bf16.bf16.f32 "
        "{%0,%1,%2,%3}, {%4,%5,%6,%7}, {%8,%9}, {%0,%1,%2,%3};"
        : "+f"(c[0]), "+f"(c[1]), "+f"(c[2]), "+f"(c[3])
        : "r"(a[0]), "r"(a[1]), "r"(a[2]), "r"(a[3]), "r"(b[0]), "r"(b[1]));
}

// ---------------------------------------------------------------------------
// bf16 HMMA GEMM:  C[8192,1024] = A'[8192,3072] * B'[1024,3072]^T  (+bias)
// CTA 128x128, 8 warps (64x32 warp tiles), BK=64, 3-stage cp.async, SW128.
// ---------------------------------------------------------------------------
#define BKB      128u            // bytes per smem row (64 bf16)
#define TILE_BYTES 16384u        // 128 rows * 128 B
#define STAGE_B  (2u * TILE_BYTES)  // A + B = 32 KB
#define GEMM_SMEM (3u * STAGE_B)    // 96 KB
#define NCHUNK   (KP / 64)       // 48

__global__ void __launch_bounds__(256, 2) gemm_hmma(
    const __nv_bfloat16* __restrict__ A, const __nv_bfloat16* __restrict__ B,
    float* __restrict__ C, const float* __restrict__ bias)
{
    const int tid  = threadIdx.x;
    const int wid  = tid >> 5;
    const int lane = tid & 31;
    const int m0   = blockIdx.y * 128;
    const int n0   = blockIdx.x * 128;
    const uint32_t sb = smem_u32(dsmem);

    const int warp_m = (wid & 1) * 64;
    const int warp_n = (wid >> 1) * 32;

    // cp.async thread mapping: id -> (row = id>>3, 16B-chunk c = id&7)
    const int lr = tid >> 3;       // rows handled per iter: tid-based
    const int lc = tid & 7;
    const uint32_t sw_st = (uint32_t)((lr & 7) * 16);  // SW128 xor for this row

    // ldmatrix address components (xor value = (row&7)*16 = ri*16 for all frags)
    const int g  = lane >> 3;
    const int ri = lane & 7;
    const uint32_t xorv = (uint32_t)(ri * 16);
    // A: rows warp_m + (g&1)*8 + ri + fm*16 ; k byte (g>>1)*16 + ki*32
    const uint32_t rowA = (uint32_t)(warp_m + (g & 1) * 8 + ri);
    const uint32_t kA   = (uint32_t)((g >> 1) * 16);
    // B: rows warp_n + nb + (g>>1)*8 + ri ; k byte (g&1)*16 + ki*32
    const uint32_t rowB = (uint32_t)(warp_n + (g >> 1) * 8 + ri);
    const uint32_t kB   = (uint32_t)((g & 1) * 16);

    float acc[4][4][4];
#pragma unroll
    for (int i = 0; i < 4; i++)
#pragma unroll
        for (int j = 0; j < 4; j++)
#pragma unroll
            for (int q = 0; q < 4; q++) acc[i][j][q] = 0.f;

    // ---- prologue: load 3 stages ----
#pragma unroll
    for (int s = 0; s < 3; s++) {
        uint32_t st = sb + (uint32_t)s * STAGE_B;
        int kc = s * 64;
#pragma unroll
        for (int t = 0; t < 4; t++) {
            int r = lr + t * 32;
            uint32_t so = (uint32_t)(r * BKB) + (((uint32_t)(lc * 16)) ^ (uint32_t)((r & 7) * 16));
            cp16(st + so, A + (size_t)(m0 + r) * KP + kc + lc * 8);
            cp16(st + TILE_BYTES + so, B + (size_t)(n0 + r) * KP + kc + lc * 8);
        }
        CP_COMMIT();
    }

    // ---- main loop ----
    for (int i = 0; i < NCHUNK; i++) {
        if (i <= NCHUNK - 4) {
            asm volatile("cp.async.wait_group 2;" ::: "memory");
        } else {
            asm volatile("cp.async.wait_group 0;" ::: "memory");
        }
        __syncthreads();

        uint32_t st  = sb + (uint32_t)(i % 3) * STAGE_B;
        uint32_t stA = st;
        uint32_t stB = st + TILE_BYTES;

#pragma unroll
        for (int ki = 0; ki < 4; ki++) {
            uint32_t a[4][4];
            uint32_t b[4][2];
#pragma unroll
            for (int fm = 0; fm < 4; fm++) {
                uint32_t row = rowA + (uint32_t)(fm * 16);
                uint32_t addr = stA + row * BKB + (((uint32_t)(ki * 32) + kA) ^ xorv);
                ldsm4(a[fm], addr);
            }
#pragma unroll
            for (int nb = 0; nb < 2; nb++) {
                uint32_t row = rowB + (uint32_t)(nb * 16);
                uint32_t addr = stB + row * BKB + (((uint32_t)(ki * 32) + kB) ^ xorv);
                uint32_t r4[4];
                ldsm4(r4, addr);
                b[nb * 2 + 0][0] = r4[0]; b[nb * 2 + 0][1] = r4[1];
                b[nb * 2 + 1][0] = r4[2]; b[nb * 2 + 1][1] = r4[3];
            }
#pragma unroll
            for (int fm = 0; fm < 4; fm++)
#pragma unroll
                for (int fn = 0; fn < 4; fn++)
                    mma16816(acc[fm][fn], a[fm], b[fn]);
        }

        __syncthreads();  // all warps done with this stage before reload

        int nk = i + 3;
        if (nk < NCHUNK) {
            uint32_t st2 = sb + (uint32_t)(nk % 3) * STAGE_B;
            int kc = nk * 64;
#pragma unroll
            for (int t = 0; t < 4; t++) {
                int r = lr + t * 32;
                uint32_t so = (uint32_t)(r * BKB) + (((uint32_t)(lc * 16)) ^ (uint32_t)((r & 7) * 16));
                cp16(st2 + so, A + (size_t)(m0 + r) * KP + kc + lc * 8);
                cp16(st2 + TILE_BYTES + so, B + (size_t)(n0 + r) * KP + kc + lc * 8);
            }
            CP_COMMIT();
        }
    }

    // ---- epilogue ----
    const int erow = lane >> 2;
    const int ecol = (lane & 3) * 2;
#pragma unroll
    for (int fm = 0; fm < 4; fm++) {
#pragma unroll
        for (int fn = 0; fn < 4; fn++) {
            int gm = m0 + warp_m + fm * 16 + erow;
            int gn = n0 + warp_n + fn * 8 + ecol;
            float2 v0 = make_float2(acc[fm][fn][0], acc[fm][fn][1]);
            float2 v1 = make_float2(acc[fm][fn][2], acc[fm][fn][3]);
            if (bias) {
                float2 bv = *(const float2*)(bias + gn);
                v0.x += bv.x; v0.y += bv.y;
                v1.x += bv.x; v1.y += bv.y;
            }
            *(float2*)(C + (size_t)gm * GN + gn) = v0;
            *(float2*)(C + (size_t)(gm + 8) * GN + gn) = v1;
        }
    }
}

// ---------------------------------------------------------------------------
// fp32 -> concatenated bf16x3 split kernels
// Row layout (uint2 = 4 bf16, 256 per 1024-col segment, 768 per row):
//   activations: [hi | hi | lo]    weights: [hi | lo | hi]
// ---------------------------------------------------------------------------
union BF4 { __nv_bfloat16 b[4]; uint2 u; };

__device__ __forceinline__ void split4(float4 v, uint2& h, uint2& l) {
    BF4 H, L;
    float f[4] = {v.x, v.y, v.z, v.w};
#pragma unroll
    for (int j = 0; j < 4; j++) {
        __nv_bfloat16 hb = __float2bfloat16(f[j]);
        H.b[j] = hb;
        L.b[j] = __float2bfloat16(f[j] - __bfloat162float(hb));
    }
    h = H.u; l = L.u;
}

__global__ void split_act(const float4* __restrict__ x, uint2* __restrict__ o, int n4)
{
    int i = blockIdx.x * blockDim.x + threadIdx.x;
    if (i >= n4) return;
    uint2 h, l;
    split4(x[i], h, l);
    size_t ob = (size_t)(i >> 8) * 768 + (i & 255);
    o[ob] = h; o[ob + 256] = h; o[ob + 512] = l;
}

__global__ void split_act_mask(const float4* __restrict__ x, const float4* __restrict__ m,
                               uint2* __restrict__ o, int n4)
{
    int i = blockIdx.x * blockDim.x + threadIdx.x;
    if (i >= n4) return;
    float4 v = x[i], mk = m[i];
    v.x *= mk.x; v.y *= mk.y; v.z *= mk.z; v.w *= mk.w;
    uint2 h, l;
    split4(v, h, l);
    size_t ob = (size_t)(i >> 8) * 768 + (i & 255);
    o[ob] = h; o[ob + 256] = h; o[ob + 512] = l;
}

__global__ void split_w(const float4* __restrict__ w, uint2* __restrict__ o, int n4)
{
    int i = blockIdx.x * blockDim.x + threadIdx.x;
    if (i >= n4) return;
    uint2 h, l;
    split4(w[i], h, l);
    size_t ob = (size_t)(i >> 8) * 768 + (i & 255);
    o[ob] = h; o[ob + 256] = l; o[ob + 512] = h;
}

// ---------------------------------------------------------------------------
// Local windowed attention (fp32, exact two-pass softmax) — unchanged
// ---------------------------------------------------------------------------
struct AttnSmem {
    float Qs[64][68];
    float KVs[64][68];
    float Ss[320][68];
    float pmax[4][64];
    float psum[4][64];
    float rowmax[64];
    float rowsum[64];
};

__global__ void __launch_bounds__(256) local_attn_kernel()
{
    AttnSmem& sm = *reinterpret_cast<AttnSmem*>(dsmem);
    const int tid   = threadIdx.x;
    const int qbase = blockIdx.x * 64;
    const int head  = blockIdx.y;
    const int b     = blockIdx.z;
    const int tx    = tid & 15;
    const int ty    = tid >> 4;
    const size_t base = ((size_t)b * CS) * CH + (size_t)head * CHD;

#pragma unroll
    for (int it = 0; it < 4; it++) {
        int idx = tid + it * 256;
        int row = idx >> 4;
        int d   = (idx & 15) * 4;
        float4 v = *(const float4*)(g_Q + base + (size_t)(qbase + row) * CH + d);
        sm.Qs[d + 0][row] = v.x; sm.Qs[d + 1][row] = v.y;
        sm.Qs[d + 2][row] = v.z; sm.Qs[d + 3][row] = v.w;
    }

    for (int kb = 0; kb < 5; kb++) {
        int kbase = qbase - CWIN + kb * 64;
        __syncthreads();
        if (kbase + 63 < 0) {
            for (int idx = tid; idx < 64 * 64; idx += 256)
                sm.Ss[kb * 64 + (idx >> 6)][idx & 63] = -1e30f;
            continue;
        }
#pragma unroll
        for (int it = 0; it < 4; it++) {
            int idx = tid + it * 256;
            int t   = idx >> 4;
            int d   = (idx & 15) * 4;
            int j   = kbase + t;
            float4 v = make_float4(0.f, 0.f, 0.f, 0.f);
            if (j >= 0)
                v = *(const float4*)(g_K + base + (size_t)j * CH + d);
            sm.KVs[d + 0][t] = v.x; sm.KVs[d + 1][t] = v.y;
            sm.KVs[d + 2][t] = v.z; sm.KVs[d + 3][t] = v.w;
        }
        __syncthreads();

        float s[4][4] = {};
#pragma unroll 16
        for (int kk = 0; kk < 64; kk++) {
            float4 av = *(const float4*)&sm.Qs[kk][ty * 4];
            float4 bv = *(const float4*)&sm.KVs[kk][tx * 4];
            float a_[4] = {av.x, av.y, av.z, av.w};
            float b_[4] = {bv.x, bv.y, bv.z, bv.w};
#pragma unroll
            for (int i = 0; i < 4; i++)
#pragma unroll
                for (int j = 0; j < 4; j++)
                    s[i][j] = fmaf(a_[i], b_[j], s[i][j]);
        }
#pragma unroll
        for (int i = 0; i < 4; i++) {
            int gi = qbase + ty * 4 + i;
#pragma unroll
            for (int j = 0; j < 4; j++) {
                int t  = tx * 4 + j;
                int gj = kbase + t;
                bool ok = (gj >= 0) && (gj <= gi) && (gj > gi - CWIN);
                sm.Ss[kb * 64 + t][ty * 4 + i] = ok ? s[i][j] : -1e30f;
            }
        }
    }
    __syncthreads();

    const int q = tid & 63;
    const int p = tid >> 6;
    {
        float mx = -1e30f;
        for (int t = p * 80; t < p * 80 + 80; t++)
            mx = fmaxf(mx, sm.Ss[t][q]);
        sm.pmax[p][q] = mx;
    }
    __syncthreads();
    if (tid < 64) {
        sm.rowmax[tid] = fmaxf(fmaxf(sm.pmax[0][tid], sm.pmax[1][tid]),
                               fmaxf(sm.pmax[2][tid], sm.pmax[3][tid]));
    }
    __syncthreads();
    {
        float rm = sm.rowmax[q];
        float sum = 0.f;
        for (int t = p * 80; t < p * 80 + 80; t++) {
            float e = __expf(sm.Ss[t][q] - rm);
            sm.Ss[t][q] = e;
            sum += e;
        }
        sm.psum[p][q] = sum;
    }
    __syncthreads();
    if (tid < 64) {
        sm.rowsum[tid] = sm.psum[0][tid] + sm.psum[1][tid] +
                         sm.psum[2][tid] + sm.psum[3][tid];
    }

    float o[4][4] = {};
    for (int kb = 0; kb < 5; kb++) {
        int kbase = qbase - CWIN + kb * 64;
        if (kbase + 63 < 0) continue;
        __syncthreads();
#pragma unroll
        for (int it = 0; it < 4; it++) {
            int idx = tid + it * 256;
            int t   = idx >> 4;
            int d   = (idx & 15) * 4;
            int j   = kbase + t;
            float4 v = make_float4(0.f, 0.f, 0.f, 0.f);
            if (j >= 0)
                v = *(const float4*)(g_V + base + (size_t)j * CH + d);
            *(float4*)&sm.KVs[t][d] = v;
        }
        __syncthreads();
#pragma unroll 16
        for (int kk = 0; kk < 64; kk++) {
            float4 av = *(const float4*)&sm.Ss[kb * 64 + kk][ty * 4];
            float4 bv = *(const float4*)&sm.KVs[kk][tx * 4];
            float a_[4] = {av.x, av.y, av.z, av.w};
            float b_[4] = {bv.x, bv.y, bv.z, bv.w};
#pragma unroll
            for (int i = 0; i < 4; i++)
#pragma unroll
                for (int j = 0; j < 4; j++)
                    o[i][j] = fmaf(a_[i], b_[j], o[i][j]);
        }
    }

#pragma unroll
    for (int i = 0; i < 4; i++) {
        float inv = 1.0f / sm.rowsum[ty * 4 + i];
        float4 v;
        v.x = o[i][0] * inv; v.y = o[i][1] * inv;
        v.z = o[i][2] * inv; v.w = o[i][3] * inv;
        *(float4*)(g_ctx + base + (size_t)(qbase + ty * 4 + i) * CH + tx * 4) = v;
    }
}

// ---------------------------------------------------------------------------
// kernel_launch
// ---------------------------------------------------------------------------
extern "C" void kernel_launch(void* const* d_in, const int* in_sizes, int n_in,
                              void* d_out, int out_size)
{
    const float* x   = (const float*)d_in[0];
    const float* xc  = (const float*)d_in[1];
    const float* abl = (const float*)d_in[2];
    const float* Wq  = (const float*)d_in[3];
    const float* Wk  = (const float*)d_in[4];
    const float* Wv  = (const float*)d_in[5];
    const float* Wo  = (const float*)d_in[6];
    const float* bo  = (const float*)d_in[7];
    float* out = (float*)d_out;

    float *qp, *kp, *vp, *cp;
    cudaGetSymbolAddress((void**)&qp, g_Q);
    cudaGetSymbolAddress((void**)&kp, g_K);
    cudaGetSymbolAddress((void**)&vp, g_V);
    cudaGetSymbolAddress((void**)&cp, g_ctx);
    __nv_bfloat16 *ax, *axc, *ac, *bq, *bk, *bv, *bo2;
    cudaGetSymbolAddress((void**)&ax,  g_Ax);
    cudaGetSymbolAddress((void**)&axc, g_Axc);
    cudaGetSymbolAddress((void**)&ac,  g_Ac);
    cudaGetSymbolAddress((void**)&bq,  g_Bq);
    cudaGetSymbolAddress((void**)&bk,  g_Bk);
    cudaGetSymbolAddress((void**)&bv,  g_Bv);
    cudaGetSymbolAddress((void**)&bo2, g_Bo);

    const int nAct4 = GM * CH / 4;   // 2M
    const int nW4   = CH * CH / 4;   // 256K

    split_act<<<(nAct4 + 255) / 256, 256>>>((const float4*)x,  (uint2*)ax,  nAct4);
    split_act<<<(nAct4 + 255) / 256, 256>>>((const float4*)xc, (uint2*)axc, nAct4);
    split_w<<<(nW4 + 255) / 256, 256>>>((const float4*)Wq, (uint2*)bq,  nW4);
    split_w<<<(nW4 + 255) / 256, 256>>>((const float4*)Wk, (uint2*)bk,  nW4);
    split_w<<<(nW4 + 255) / 256, 256>>>((const float4*)Wv, (uint2*)bv,  nW4);
    split_w<<<(nW4 + 255) / 256, 256>>>((const float4*)Wo, (uint2*)bo2, nW4);

    cudaFuncSetAttribute(gemm_hmma, cudaFuncAttributeMaxDynamicSharedMemorySize, GEMM_SMEM);
    dim3 ggrid(GN / 128, GM / 128);  // (8, 64)

    gemm_hmma<<<ggrid, 256, GEMM_SMEM>>>(ax,  bq,  qp, nullptr);
    gemm_hmma<<<ggrid, 256, GEMM_SMEM>>>(axc, bk,  kp, nullptr);
    gemm_hmma<<<ggrid, 256, GEMM_SMEM>>>(axc, bv,  vp, nullptr);

    cudaFuncSetAttribute(local_attn_kernel, cudaFuncAttributeMaxDynamicSharedMemorySize,
                         (int)sizeof(AttnSmem));
    local_attn_kernel<<<dim3(CS / 64, CNH, CB), 256, sizeof(AttnSmem)>>>();

    split_act_mask<<<(nAct4 + 255) / 256, 256>>>((const float4*)cp, (const float4*)abl,
                                                 (uint2*)ac, nAct4);

    gemm_hmma<<<ggrid, 256, GEMM_SMEM>>>(ac, bo2, out, bo);
}

// round 7
// speedup vs baseline: 2.9907x; 1.2934x over previous
#include <cuda_runtime.h>
#include <cuda_bf16.h>
#include <cstdint>

// Problem constants
#define CB   4
#define CS   2048
#define CH   1024
#define CNH  16
#define CHD  64
#define CWIN 256

#define GM   (CB * CS)   // 8192
#define GN   CH          // 1024
#define GK   CH          // 1024
#define KP   (3 * GK)    // 3072 concatenated-K for bf16x3

// ---------------------------------------------------------------------------
// Scratch (allocation-free rule: __device__ globals)
// ---------------------------------------------------------------------------
__device__ float g_Q[GM * CH];
__device__ float g_K[GM * CH];
__device__ float g_V[GM * CH];
__device__ float g_ctx[GM * CH];

// Concatenated-K bf16 operands: A' = [hi | hi | lo], B' = [hi | lo | hi]
__device__ __nv_bfloat16 g_Ax[GM * KP];    // from x
__device__ __nv_bfloat16 g_Axc[GM * KP];   // from x_clean
__device__ __nv_bfloat16 g_Ac[GM * KP];    // from ctx * ablation_mask
__device__ __nv_bfloat16 g_Bq[GN * KP];
__device__ __nv_bfloat16 g_Bk[GN * KP];
__device__ __nv_bfloat16 g_Bv[GN * KP];
__device__ __nv_bfloat16 g_Bo[GN * KP];

extern __shared__ char dsmem[];

// ---------------------------------------------------------------------------
// Helpers
// ---------------------------------------------------------------------------
__device__ __forceinline__ uint32_t smem_u32(const void* p) {
    uint32_t a;
    asm("{ .reg .u64 t; cvta.to.shared.u64 t, %1; cvt.u32.u64 %0, t; }"
        : "=r"(a) : "l"(p));
    return a;
}

__device__ __forceinline__ void cp16(uint32_t dst, const void* src) {
    asm volatile("cp.async.cg.shared.global [%0], [%1], 16;" :: "r"(dst), "l"(src) : "memory");
}
#define CP_COMMIT() asm volatile("cp.async.commit_group;" ::: "memory")

__device__ __forceinline__ void ldsm4(uint32_t* r, uint32_t addr) {
    asm volatile("ldmatrix.sync.aligned.m8n8.x4.shared.b16 {%0,%1,%2,%3}, [%4];"
                 : "=r"(r[0]), "=r"(r[1]), "=r"(r[2]), "=r"(r[3]) : "r"(addr));
}

__device__ __forceinline__ void ldsm4t(uint32_t* r, uint32_t addr) {
    asm volatile("ldmatrix.sync.aligned.m8n8.x4.trans.shared.b16 {%0,%1,%2,%3}, [%4];"
                 : "=r"(r[0]), "=r"(r[1]), "=r"(r[2]), "=r"(r[3]) : "r"(addr));
}

__device__ __forceinline__ void mma16816(float* c, const uint32_t* a, const uint32_t* b) {
    asm volatile(
        "mma.sync.aligned.m16n8k16.row.col.f32.bf16.bf16.f32 "
        "{%0,%1,%2,%3}, {%4,%5,%6,%7}, {%8,%9}, {%0,%1,%2,%3};"
        : "+f"(c[0]), "+f"(c[1]), "+f"(c[2]), "+f"(c[3])
        : "r"(a[0]), "r"(a[1]), "r"(a[2]), "r"(a[3]), "r"(b[0]), "r"(b[1]));
}

// pack two floats as bf16x2: low half = e0, high half = e1 ; plus residual pack
__device__ __forceinline__ void split_pack2(float e0, float e1, uint32_t& h, uint32_t& l) {
    __nv_bfloat16 b0 = __float2bfloat16(e0), b1 = __float2bfloat16(e1);
    __nv_bfloat162 hb; hb.x = b0; hb.y = b1;
    h = *reinterpret_cast<uint32_t*>(&hb);
    float r0 = e0 - __bfloat162float(b0);
    float r1 = e1 - __bfloat162float(b1);
    __nv_bfloat162 lb; lb.x = __float2bfloat16(r0); lb.y = __float2bfloat16(r1);
    l = *reinterpret_cast<uint32_t*>(&lb);
}

// smem tile address: row r (0..63), 16B chunk c (0..7), swizzled
__device__ __forceinline__ uint32_t tile_addr(uint32_t base, int r, int c) {
    return base + (uint32_t)(r * 128) + (uint32_t)(((c ^ (r & 7)) << 4));
}

// ---------------------------------------------------------------------------
// bf16 HMMA GEMM:  C[8192,1024] = A'[8192,3072] * B'[1024,3072]^T  (+bias)
// CTA 128x128, 8 warps (64x32 warp tiles), BK=64, 3-stage cp.async, SW128.
// ---------------------------------------------------------------------------
#define BKB      128u            // bytes per smem row (64 bf16)
#define TILE_BYTES 16384u        // 128 rows * 128 B
#define STAGE_B  (2u * TILE_BYTES)  // A + B = 32 KB
#define GEMM_SMEM (3u * STAGE_B)    // 96 KB
#define NCHUNK   (KP / 64)       // 48

__global__ void __launch_bounds__(256, 2) gemm_hmma(
    const __nv_bfloat16* __restrict__ A, const __nv_bfloat16* __restrict__ B,
    float* __restrict__ C, const float* __restrict__ bias)
{
    const int tid  = threadIdx.x;
    const int wid  = tid >> 5;
    const int lane = tid & 31;
    const int m0   = blockIdx.y * 128;
    const int n0   = blockIdx.x * 128;
    const uint32_t sb = smem_u32(dsmem);

    const int warp_m = (wid & 1) * 64;
    const int warp_n = (wid >> 1) * 32;

    const int lr = tid >> 3;
    const int lc = tid & 7;

    const int g  = lane >> 3;
    const int ri = lane & 7;
    const uint32_t xorv = (uint32_t)(ri * 16);
    const uint32_t rowA = (uint32_t)(warp_m + (g & 1) * 8 + ri);
    const uint32_t kA   = (uint32_t)((g >> 1) * 16);
    const uint32_t rowB = (uint32_t)(warp_n + (g >> 1) * 8 + ri);
    const uint32_t kB   = (uint32_t)((g & 1) * 16);

    float acc[4][4][4];
#pragma unroll
    for (int i = 0; i < 4; i++)
#pragma unroll
        for (int j = 0; j < 4; j++)
#pragma unroll
            for (int q = 0; q < 4; q++) acc[i][j][q] = 0.f;

#pragma unroll
    for (int s = 0; s < 3; s++) {
        uint32_t st = sb + (uint32_t)s * STAGE_B;
        int kc = s * 64;
#pragma unroll
        for (int t = 0; t < 4; t++) {
            int r = lr + t * 32;
            uint32_t so = (uint32_t)(r * BKB) + (((uint32_t)(lc * 16)) ^ (uint32_t)((r & 7) * 16));
            cp16(st + so, A + (size_t)(m0 + r) * KP + kc + lc * 8);
            cp16(st + TILE_BYTES + so, B + (size_t)(n0 + r) * KP + kc + lc * 8);
        }
        CP_COMMIT();
    }

    for (int i = 0; i < NCHUNK; i++) {
        if (i <= NCHUNK - 4) {
            asm volatile("cp.async.wait_group 2;" ::: "memory");
        } else {
            asm volatile("cp.async.wait_group 0;" ::: "memory");
        }
        __syncthreads();

        uint32_t st  = sb + (uint32_t)(i % 3) * STAGE_B;
        uint32_t stA = st;
        uint32_t stB = st + TILE_BYTES;

#pragma unroll
        for (int ki = 0; ki < 4; ki++) {
            uint32_t a[4][4];
            uint32_t b[4][2];
#pragma unroll
            for (int fm = 0; fm < 4; fm++) {
                uint32_t row = rowA + (uint32_t)(fm * 16);
                uint32_t addr = stA + row * BKB + (((uint32_t)(ki * 32) + kA) ^ xorv);
                ldsm4(a[fm], addr);
            }
#pragma unroll
            for (int nb = 0; nb < 2; nb++) {
                uint32_t row = rowB + (uint32_t)(nb * 16);
                uint32_t addr = stB + row * BKB + (((uint32_t)(ki * 32) + kB) ^ xorv);
                uint32_t r4[4];
                ldsm4(r4, addr);
                b[nb * 2 + 0][0] = r4[0]; b[nb * 2 + 0][1] = r4[1];
                b[nb * 2 + 1][0] = r4[2]; b[nb * 2 + 1][1] = r4[3];
            }
#pragma unroll
            for (int fm = 0; fm < 4; fm++)
#pragma unroll
                for (int fn = 0; fn < 4; fn++)
                    mma16816(acc[fm][fn], a[fm], b[fn]);
        }

        __syncthreads();

        int nk = i + 3;
        if (nk < NCHUNK) {
            uint32_t st2 = sb + (uint32_t)(nk % 3) * STAGE_B;
            int kc = nk * 64;
#pragma unroll
            for (int t = 0; t < 4; t++) {
                int r = lr + t * 32;
                uint32_t so = (uint32_t)(r * BKB) + (((uint32_t)(lc * 16)) ^ (uint32_t)((r & 7) * 16));
                cp16(st2 + so, A + (size_t)(m0 + r) * KP + kc + lc * 8);
                cp16(st2 + TILE_BYTES + so, B + (size_t)(n0 + r) * KP + kc + lc * 8);
            }
            CP_COMMIT();
        }
    }

    const int erow = lane >> 2;
    const int ecol = (lane & 3) * 2;
#pragma unroll
    for (int fm = 0; fm < 4; fm++) {
#pragma unroll
        for (int fn = 0; fn < 4; fn++) {
            int gm = m0 + warp_m + fm * 16 + erow;
            int gn = n0 + warp_n + fn * 8 + ecol;
            float2 v0 = make_float2(acc[fm][fn][0], acc[fm][fn][1]);
            float2 v1 = make_float2(acc[fm][fn][2], acc[fm][fn][3]);
            if (bias) {
                float2 bv = *(const float2*)(bias + gn);
                v0.x += bv.x; v0.y += bv.y;
                v1.x += bv.x; v1.y += bv.y;
            }
            *(float2*)(C + (size_t)gm * GN + gn) = v0;
            *(float2*)(C + (size_t)(gm + 8) * GN + gn) = v1;
        }
    }
}

// ---------------------------------------------------------------------------
// fp32 -> concatenated bf16x3 split kernels
// ---------------------------------------------------------------------------
union BF4 { __nv_bfloat16 b[4]; uint2 u; };

__device__ __forceinline__ void split4(float4 v, uint2& h, uint2& l) {
    BF4 H, L;
    float f[4] = {v.x, v.y, v.z, v.w};
#pragma unroll
    for (int j = 0; j < 4; j++) {
        __nv_bfloat16 hb = __float2bfloat16(f[j]);
        H.b[j] = hb;
        L.b[j] = __float2bfloat16(f[j] - __bfloat162float(hb));
    }
    h = H.u; l = L.u;
}

__global__ void split_act(const float4* __restrict__ x, uint2* __restrict__ o, int n4)
{
    int i = blockIdx.x * blockDim.x + threadIdx.x;
    if (i >= n4) return;
    uint2 h, l;
    split4(x[i], h, l);
    size_t ob = (size_t)(i >> 8) * 768 + (i & 255);
    o[ob] = h; o[ob + 256] = h; o[ob + 512] = l;
}

__global__ void split_act_mask(const float4* __restrict__ x, const float4* __restrict__ m,
                               uint2* __restrict__ o, int n4)
{
    int i = blockIdx.x * blockDim.x + threadIdx.x;
    if (i >= n4) return;
    float4 v = x[i], mk = m[i];
    v.x *= mk.x; v.y *= mk.y; v.z *= mk.z; v.w *= mk.w;
    uint2 h, l;
    split4(v, h, l);
    size_t ob = (size_t)(i >> 8) * 768 + (i & 255);
    o[ob] = h; o[ob + 256] = h; o[ob + 512] = l;
}

__global__ void split_w(const float4* __restrict__ w, uint2* __restrict__ o, int n4)
{
    int i = blockIdx.x * blockDim.x + threadIdx.x;
    if (i >= n4) return;
    uint2 h, l;
    split4(w[i], h, l);
    size_t ob = (size_t)(i >> 8) * 768 + (i & 255);
    o[ob] = h; o[ob + 256] = l; o[ob + 512] = h;
}

// ---------------------------------------------------------------------------
// HMMA local attention with online softmax (flash-style, bf16x3 split).
// One CTA = 64 queries x 1 head x 1 batch. 4 warps, each 16 query rows.
// Smem: Q/K/V hi+lo, 64x64 bf16 tiles, 128B rows, 16B-chunk swizzle.
// S = QhKh + QhKl + QlKh ; O += PhVh + PhVl + PlVh  (fp32 accum everywhere)
// ---------------------------------------------------------------------------
#define ATT_SMEM 49152

// fp32 64x64 tile -> hi/lo bf16 swizzled smem tiles (128 threads)
__device__ __forceinline__ void cvt_load64(const float* __restrict__ src,
                                           uint32_t dh, uint32_t dl, int tid)
{
    int r = tid >> 1, half = tid & 1;
    const float* p = src + (size_t)r * CH + half * 32;
#pragma unroll
    for (int c4 = 0; c4 < 4; c4++) {
        float4 v0 = *(const float4*)(p + c4 * 8);
        float4 v1 = *(const float4*)(p + c4 * 8 + 4);
        uint32_t h0, L0, h1, L1, h2, L2, h3, L3;
        split_pack2(v0.x, v0.y, h0, L0);
        split_pack2(v0.z, v0.w, h1, L1);
        split_pack2(v1.x, v1.y, h2, L2);
        split_pack2(v1.z, v1.w, h3, L3);
        int chunk = half * 4 + c4;
        uint32_t off = (uint32_t)(r * 128) + (uint32_t)(((chunk ^ (r & 7)) << 4));
        asm volatile("st.shared.v4.b32 [%0], {%1,%2,%3,%4};"
                     :: "r"(dh + off), "r"(h0), "r"(h1), "r"(h2), "r"(h3) : "memory");
        asm volatile("st.shared.v4.b32 [%0], {%1,%2,%3,%4};"
                     :: "r"(dl + off), "r"(L0), "r"(L1), "r"(L2), "r"(L3) : "memory");
    }
}

__global__ void __launch_bounds__(128, 3) attn_hmma_kernel()
{
    const uint32_t sb = smem_u32(dsmem);
    const uint32_t sQh = sb,          sQl = sb + 8192;
    const uint32_t sKh = sb + 16384,  sKl = sb + 24576;
    const uint32_t sVh = sb + 32768,  sVl = sb + 40960;

    const int tid  = threadIdx.x;
    const int lane = tid & 31;
    const int wq   = tid >> 5;           // warp -> query rows wq*16..+15
    const int qbase = blockIdx.x * 64;
    const int head  = blockIdx.y;
    const int bb    = blockIdx.z;
    const size_t base = (size_t)bb * CS * CH + (size_t)head * CHD;

    const int idx = lane >> 3;           // ldmatrix tile index 0..3
    const int lo7 = lane & 7;

    // Load + split Q tile
    cvt_load64(g_Q + base + (size_t)qbase * CH, sQh, sQl, tid);
    __syncthreads();

    // Q A-fragments (persistent): [kiter][4]
    uint32_t qh[4][4], ql[4][4];
    {
        int q = wq * 16 + (idx & 1) * 8 + lo7;
#pragma unroll
        for (int ki = 0; ki < 4; ki++) {
            int ch = 2 * ki + (idx >> 1);
            ldsm4(qh[ki], tile_addr(sQh, q, ch));
            ldsm4(ql[ki], tile_addr(sQl, q, ch));
        }
    }

    float O[8][4];
#pragma unroll
    for (int f = 0; f < 8; f++)
#pragma unroll
        for (int c = 0; c < 4; c++) O[f][c] = 0.f;
    float m0 = -1e30f, m1 = -1e30f, l0 = 0.f, l1 = 0.f;

    const int i0 = qbase + wq * 16 + (lane >> 2);
    const int i1 = i0 + 8;

    for (int kb = 0; kb < 5; kb++) {
        int kbase = qbase - CWIN + kb * 64;
        if (kbase < 0) continue;
        __syncthreads();
        cvt_load64(g_K + base + (size_t)kbase * CH, sKh, sKl, tid);
        cvt_load64(g_V + base + (size_t)kbase * CH, sVh, sVl, tid);
        __syncthreads();

        // ---- S = Q K^T (64q x 64t), 8 n-frags x fp32 ----
        float SF[8][4];
#pragma unroll
        for (int f = 0; f < 8; f++)
#pragma unroll
            for (int c = 0; c < 4; c++) SF[f][c] = 0.f;

#pragma unroll
        for (int ki = 0; ki < 4; ki++) {
#pragma unroll
            for (int tg = 0; tg < 4; tg++) {
                int t = tg * 16 + (idx & 1) * 8 + lo7;
                int ch = 2 * ki + (idx >> 1);
                uint32_t kh4[4], kl4[4];
                ldsm4(kh4, tile_addr(sKh, t, ch));
                ldsm4(kl4, tile_addr(sKl, t, ch));
                uint32_t b0[2] = {kh4[0], kh4[2]};
                uint32_t b1[2] = {kh4[1], kh4[3]};
                uint32_t c0[2] = {kl4[0], kl4[2]};
                uint32_t c1[2] = {kl4[1], kl4[3]};
                mma16816(SF[tg * 2],     qh[ki], b0);
                mma16816(SF[tg * 2 + 1], qh[ki], b1);
                mma16816(SF[tg * 2],     qh[ki], c0);
                mma16816(SF[tg * 2 + 1], qh[ki], c1);
                mma16816(SF[tg * 2],     ql[ki], b0);
                mma16816(SF[tg * 2 + 1], ql[ki], b1);
            }
        }

        // ---- mask + online softmax ----
        float mx0 = -1e30f, mx1 = -1e30f;
#pragma unroll
        for (int f = 0; f < 8; f++) {
            int j0 = kbase + f * 8 + 2 * (lane & 3);
            int j1 = j0 + 1;
            if (!(j0 <= i0 && j0 > i0 - CWIN)) SF[f][0] = -1e30f;
            if (!(j1 <= i0 && j1 > i0 - CWIN)) SF[f][1] = -1e30f;
            if (!(j0 <= i1 && j0 > i1 - CWIN)) SF[f][2] = -1e30f;
            if (!(j1 <= i1 && j1 > i1 - CWIN)) SF[f][3] = -1e30f;
            mx0 = fmaxf(mx0, fmaxf(SF[f][0], SF[f][1]));
            mx1 = fmaxf(mx1, fmaxf(SF[f][2], SF[f][3]));
        }
        mx0 = fmaxf(mx0, __shfl_xor_sync(0xFFFFFFFFu, mx0, 1));
        mx0 = fmaxf(mx0, __shfl_xor_sync(0xFFFFFFFFu, mx0, 2));
        mx1 = fmaxf(mx1, __shfl_xor_sync(0xFFFFFFFFu, mx1, 1));
        mx1 = fmaxf(mx1, __shfl_xor_sync(0xFFFFFFFFu, mx1, 2));

        float mn0 = fmaxf(fmaxf(m0, mx0), -1e20f);
        float mn1 = fmaxf(fmaxf(m1, mx1), -1e20f);
        float sc0 = __expf(m0 - mn0);
        float sc1 = __expf(m1 - mn1);

        float s0 = 0.f, s1 = 0.f;
#pragma unroll
        for (int f = 0; f < 8; f++) {
            SF[f][0] = __expf(SF[f][0] - mn0);
            SF[f][1] = __expf(SF[f][1] - mn0);
            SF[f][2] = __expf(SF[f][2] - mn1);
            SF[f][3] = __expf(SF[f][3] - mn1);
            s0 += SF[f][0] + SF[f][1];
            s1 += SF[f][2] + SF[f][3];
        }
        s0 += __shfl_xor_sync(0xFFFFFFFFu, s0, 1);
        s0 += __shfl_xor_sync(0xFFFFFFFFu, s0, 2);
        s1 += __shfl_xor_sync(0xFFFFFFFFu, s1, 1);
        s1 += __shfl_xor_sync(0xFFFFFFFFu, s1, 2);
        l0 = l0 * sc0 + s0;
        l1 = l1 * sc1 + s1;
        m0 = mn0; m1 = mn1;

#pragma unroll
        for (int f = 0; f < 8; f++) {
            O[f][0] *= sc0; O[f][1] *= sc0;
            O[f][2] *= sc1; O[f][3] *= sc1;
        }

        // ---- O += P V (P register-resident, split hi/lo) ----
#pragma unroll
        for (int kt = 0; kt < 4; kt++) {
            uint32_t pah[4], pal[4];
            split_pack2(SF[2 * kt][0],     SF[2 * kt][1],     pah[0], pal[0]);
            split_pack2(SF[2 * kt][2],     SF[2 * kt][3],     pah[1], pal[1]);
            split_pack2(SF[2 * kt + 1][0], SF[2 * kt + 1][1], pah[2], pal[2]);
            split_pack2(SF[2 * kt + 1][2], SF[2 * kt + 1][3], pah[3], pal[3]);
#pragma unroll
            for (int dg = 0; dg < 4; dg++) {
                int t = kt * 16 + (idx & 1) * 8 + lo7;
                int ch = 2 * dg + (idx >> 1);
                uint32_t vh4[4], vl4[4];
                ldsm4t(vh4, tile_addr(sVh, t, ch));
                ldsm4t(vl4, tile_addr(sVl, t, ch));
                uint32_t b0h[2] = {vh4[0], vh4[1]};
                uint32_t b1h[2] = {vh4[2], vh4[3]};
                uint32_t b0l[2] = {vl4[0], vl4[1]};
                uint32_t b1l[2] = {vl4[2], vl4[3]};
                mma16816(O[2 * dg],     pah, b0h);
                mma16816(O[2 * dg + 1], pah, b1h);
                mma16816(O[2 * dg],     pah, b0l);
                mma16816(O[2 * dg + 1], pah, b1l);
                mma16816(O[2 * dg],     pal, b0h);
                mma16816(O[2 * dg + 1], pal, b1h);
            }
        }
    }

    // ---- epilogue: normalize and write context (merged-head layout) ----
    float inv0 = 1.0f / l0;
    float inv1 = 1.0f / l1;
#pragma unroll
    for (int f = 0; f < 8; f++) {
        int col = f * 8 + 2 * (lane & 3);
        float2 v0 = make_float2(O[f][0] * inv0, O[f][1] * inv0);
        float2 v1 = make_float2(O[f][2] * inv1, O[f][3] * inv1);
        *(float2*)(g_ctx + base + (size_t)i0 * CH + col) = v0;
        *(float2*)(g_ctx + base + (size_t)i1 * CH + col) = v1;
    }
}

// ---------------------------------------------------------------------------
// kernel_launch
// ---------------------------------------------------------------------------
extern "C" void kernel_launch(void* const* d_in, const int* in_sizes, int n_in,
                              void* d_out, int out_size)
{
    const float* x   = (const float*)d_in[0];
    const float* xc  = (const float*)d_in[1];
    const float* abl = (const float*)d_in[2];
    const float* Wq  = (const float*)d_in[3];
    const float* Wk  = (const float*)d_in[4];
    const float* Wv  = (const float*)d_in[5];
    const float* Wo  = (const float*)d_in[6];
    const float* bo  = (const float*)d_in[7];
    float* out = (float*)d_out;

    float *qp, *kp, *vp, *cp;
    cudaGetSymbolAddress((void**)&qp, g_Q);
    cudaGetSymbolAddress((void**)&kp, g_K);
    cudaGetSymbolAddress((void**)&vp, g_V);
    cudaGetSymbolAddress((void**)&cp, g_ctx);
    __nv_bfloat16 *ax, *axc, *ac, *bq, *bk, *bv, *bo2;
    cudaGetSymbolAddress((void**)&ax,  g_Ax);
    cudaGetSymbolAddress((void**)&axc, g_Axc);
    cudaGetSymbolAddress((void**)&ac,  g_Ac);
    cudaGetSymbolAddress((void**)&bq,  g_Bq);
    cudaGetSymbolAddress((void**)&bk,  g_Bk);
    cudaGetSymbolAddress((void**)&bv,  g_Bv);
    cudaGetSymbolAddress((void**)&bo2, g_Bo);

    const int nAct4 = GM * CH / 4;
    const int nW4   = CH * CH / 4;

    split_act<<<(nAct4 + 255) / 256, 256>>>((const float4*)x,  (uint2*)ax,  nAct4);
    split_act<<<(nAct4 + 255) / 256, 256>>>((const float4*)xc, (uint2*)axc, nAct4);
    split_w<<<(nW4 + 255) / 256, 256>>>((const float4*)Wq, (uint2*)bq,  nW4);
    split_w<<<(nW4 + 255) / 256, 256>>>((const float4*)Wk, (uint2*)bk,  nW4);
    split_w<<<(nW4 + 255) / 256, 256>>>((const float4*)Wv, (uint2*)bv,  nW4);
    split_w<<<(nW4 + 255) / 256, 256>>>((const float4*)Wo, (uint2*)bo2, nW4);

    cudaFuncSetAttribute(gemm_hmma, cudaFuncAttributeMaxDynamicSharedMemorySize, GEMM_SMEM);
    dim3 ggrid(GN / 128, GM / 128);

    gemm_hmma<<<ggrid, 256, GEMM_SMEM>>>(ax,  bq,  qp, nullptr);
    gemm_hmma<<<ggrid, 256, GEMM_SMEM>>>(axc, bk,  kp, nullptr);
    gemm_hmma<<<ggrid, 256, GEMM_SMEM>>>(axc, bv,  vp, nullptr);

    cudaFuncSetAttribute(attn_hmma_kernel, cudaFuncAttributeMaxDynamicSharedMemorySize, ATT_SMEM);
    attn_hmma_kernel<<<dim3(CS / 64, CNH, CB), 128, ATT_SMEM>>>();

    split_act_mask<<<(nAct4 + 255) / 256, 256>>>((const float4*)cp, (const float4*)abl,
                                                 (uint2*)ac, nAct4);

    gemm_hmma<<<ggrid, 256, GEMM_SMEM>>>(ac, bo2, out, bo);
}

// round 9
// speedup vs baseline: 3.2913x; 1.1005x over previous
#include <cuda_runtime.h>
#include <cuda_bf16.h>
#include <cstdint>

// Problem constants
#define CB   4
#define CS   2048
#define CH   1024
#define CNH  16
#define CHD  64
#define CWIN 256

#define GM   (CB * CS)   // 8192
#define GN   CH          // 1024
#define GK   CH          // 1024
#define KD   (2 * GK)    // 2048: [hi | lo] layout width

// ---------------------------------------------------------------------------
// Scratch (allocation-free rule: __device__ globals)
// ---------------------------------------------------------------------------
__device__ float g_Q[GM * CH];
__device__ float g_K[GM * CH];
__device__ float g_V[GM * CH];
__device__ float g_ctx[GM * CH];

// [hi | lo] bf16 operands (row-major, width KD)
__device__ __nv_bfloat16 g_Ax[GM * KD];    // from x
__device__ __nv_bfloat16 g_Axc[GM * KD];   // from x_clean
__device__ __nv_bfloat16 g_Ac[GM * KD];    // from ctx * ablation_mask
__device__ __nv_bfloat16 g_Bq[GN * KD];
__device__ __nv_bfloat16 g_Bk[GN * KD];
__device__ __nv_bfloat16 g_Bv[GN * KD];
__device__ __nv_bfloat16 g_Bo[GN * KD];

extern __shared__ char dsmem[];

// ---------------------------------------------------------------------------
// Helpers
// ---------------------------------------------------------------------------
__device__ __forceinline__ uint32_t smem_u32(const void* p) {
    uint32_t a;
    asm("{ .reg .u64 t; cvta.to.shared.u64 t, %1; cvt.u32.u64 %0, t; }"
        : "=r"(a) : "l"(p));
    return a;
}

__device__ __forceinline__ void cp16(uint32_t dst, const void* src) {
    asm volatile("cp.async.cg.shared.global [%0], [%1], 16;" :: "r"(dst), "l"(src) : "memory");
}
#define CP_COMMIT() asm volatile("cp.async.commit_group;" ::: "memory")

__device__ __forceinline__ void ldsm4(uint32_t* r, uint32_t addr) {
    asm volatile("ldmatrix.sync.aligned.m8n8.x4.shared.b16 {%0,%1,%2,%3}, [%4];"
                 : "=r"(r[0]), "=r"(r[1]), "=r"(r[2]), "=r"(r[3]) : "r"(addr));
}

__device__ __forceinline__ void ldsm4t(uint32_t* r, uint32_t addr) {
    asm volatile("ldmatrix.sync.aligned.m8n8.x4.trans.shared.b16 {%0,%1,%2,%3}, [%4];"
                 : "=r"(r[0]), "=r"(r[1]), "=r"(r[2]), "=r"(r[3]) : "r"(addr));
}

__device__ __forceinline__ void mma16816(float* c, const uint32_t* a, const uint32_t* b) {
    asm volatile(
        "mma.sync.aligned.m16n8k16.row.col.f32.bf16.bf16.f32 "
        "{%0,%1,%2,%3}, {%4,%5,%6,%7}, {%8,%9}, {%0,%1,%2,%3};"
        : "+f"(c[0]), "+f"(c[1]), "+f"(c[2]), "+f"(c[3])
        : "r"(a[0]), "r"(a[1]), "r"(a[2]), "r"(a[3]), "r"(b[0]), "r"(b[1]));
}

__device__ __forceinline__ void split_pack2(float e0, float e1, uint32_t& h, uint32_t& l) {
    __nv_bfloat16 b0 = __float2bfloat16(e0), b1 = __float2bfloat16(e1);
    __nv_bfloat162 hb; hb.x = b0; hb.y = b1;
    h = *reinterpret_cast<uint32_t*>(&hb);
    float r0 = e0 - __bfloat162float(b0);
    float r1 = e1 - __bfloat162float(b1);
    __nv_bfloat162 lb; lb.x = __float2bfloat16(r0); lb.y = __float2bfloat16(r1);
    l = *reinterpret_cast<uint32_t*>(&lb);
}

// smem tile address: row r, 16B chunk c (0..7), 128B rows, swizzled
__device__ __forceinline__ uint32_t tile_addr(uint32_t base, int r, int c) {
    return base + (uint32_t)(r * 128) + (uint32_t)(((c ^ (r & 7)) << 4));
}

// ---------------------------------------------------------------------------
// bf16x3 HMMA GEMM (fragment-reuse form):
//   C[8192,1024] = Ah*Bh^T + Ah*Bl^T + Al*Bh^T  (+bias)
// CTA 128x256, 8 warps (64x64 warp tiles), BK=64, 2-stage cp.async, SW128.
// A/B stored [hi | lo] row-major width KD.
// ---------------------------------------------------------------------------
#define T_AH 0u
#define T_AL 16384u
#define T_BH 32768u
#define T_BL 65536u
#define STAGE_B 98304u            // 96 KB
#define GEMM_SMEM (2u * STAGE_B)  // 192 KB
#define NCHUNK 16                 // GK / 64

__device__ __forceinline__ void g_load_stage(
    uint32_t st, const __nv_bfloat16* __restrict__ A, const __nv_bfloat16* __restrict__ B,
    int m0, int n0, int kc, int tid)
{
#pragma unroll
    for (int t = 0; t < 4; t++) {          // A: 128 rows x 8 chunks (hi+lo)
        int id = tid + t * 256;
        int r = id >> 3, c = id & 7;
        uint32_t so = (uint32_t)(r * 128) + (uint32_t)(((c ^ (r & 7)) << 4));
        const __nv_bfloat16* src = A + (size_t)(m0 + r) * KD + kc + c * 8;
        cp16(st + T_AH + so, src);
        cp16(st + T_AL + so, src + GK);
    }
#pragma unroll
    for (int t = 0; t < 8; t++) {          // B: 256 rows x 8 chunks (hi+lo)
        int id = tid + t * 256;
        int r = id >> 3, c = id & 7;
        uint32_t so = (uint32_t)(r * 128) + (uint32_t)(((c ^ (r & 7)) << 4));
        const __nv_bfloat16* src = B + (size_t)(n0 + r) * KD + kc + c * 8;
        cp16(st + T_BH + so, src);
        cp16(st + T_BL + so, src + GK);
    }
    CP_COMMIT();
}

__global__ void __launch_bounds__(256, 1) gemm_hmma(
    const __nv_bfloat16* __restrict__ A, const __nv_bfloat16* __restrict__ B,
    float* __restrict__ C, const float* __restrict__ bias)
{
    const int tid  = threadIdx.x;
    const int wid  = tid >> 5;
    const int lane = tid & 31;
    const int m0   = blockIdx.y * 128;
    const int n0   = blockIdx.x * 256;
    const uint32_t sb = smem_u32(dsmem);

    const int warp_m = (wid & 1) * 64;
    const int warp_n = (wid >> 1) * 64;

    const int idx = lane >> 3;
    const int lo7 = lane & 7;
    const uint32_t xorv = (uint32_t)(lo7 * 16);
    // A: matrix0..3 = (m0-7,k0-7)(m8-15,k0-7)(m0-7,k8-15)(m8-15,k8-15)? NO:
    // rowA uses (idx&1)*8 -> m-half per idx parity; kA uses (idx>>1)*16.
    //   idx0: m0-7,k0-7  idx1: m8-15,k0-7  idx2: m0-7,k8-15  idx3: m8-15,k8-15
    // -> matches mma a0..a3 directly.
    const uint32_t rowA = (uint32_t)(warp_m + (idx & 1) * 8 + lo7);
    const uint32_t kA   = (uint32_t)((idx >> 1) * 16);
    // B: rowB uses (idx>>1)*8, kB uses (idx&1)*16:
    //   idx0: n0-7,k0-7  idx1: n0-7,k8-15  idx2: n8-15,k0-7  idx3: n8-15,k8-15
    // -> n-tile0 frag = {r0,r1}, n-tile1 frag = {r2,r3}.
    const uint32_t rowB = (uint32_t)(warp_n + (idx >> 1) * 8 + lo7);
    const uint32_t kB   = (uint32_t)((idx & 1) * 16);

    float acc[4][8][4];
#pragma unroll
    for (int i = 0; i < 4; i++)
#pragma unroll
        for (int j = 0; j < 8; j++)
#pragma unroll
            for (int q = 0; q < 4; q++) acc[i][j][q] = 0.f;

    // prologue: stages 0,1
    g_load_stage(sb, A, B, m0, n0, 0, tid);
    g_load_stage(sb + STAGE_B, A, B, m0, n0, 64, tid);

    for (int i = 0; i < NCHUNK; i++) {
        if (i < NCHUNK - 1) {
            asm volatile("cp.async.wait_group 1;" ::: "memory");
        } else {
            asm volatile("cp.async.wait_group 0;" ::: "memory");
        }
        __syncthreads();

        uint32_t st = sb + (uint32_t)(i & 1) * STAGE_B;

#pragma unroll
        for (int ki = 0; ki < 4; ki++) {
            uint32_t koff = (uint32_t)(ki * 32);
            // A fragments: hi + lo (reused across 3 terms)
            uint32_t ah[4][4], al[4][4];
#pragma unroll
            for (int fm = 0; fm < 4; fm++) {
                uint32_t row = rowA + (uint32_t)(fm * 16);
                uint32_t off = row * 128u + ((koff + kA) ^ xorv);
                ldsm4(ah[fm], st + T_AH + off);
                ldsm4(al[fm], st + T_AL + off);
            }
#pragma unroll
            for (int nb = 0; nb < 4; nb++) {
                uint32_t row = rowB + (uint32_t)(nb * 16);
                uint32_t off = row * 128u + ((koff + kB) ^ xorv);
                uint32_t bh4[4], bl4[4];
                ldsm4(bh4, st + T_BH + off);
                ldsm4(bl4, st + T_BL + off);
                // FIXED pairing: n-tile0 = {r0,r1}, n-tile1 = {r2,r3}
                uint32_t b0h[2] = {bh4[0], bh4[1]};
                uint32_t b1h[2] = {bh4[2], bh4[3]};
                uint32_t b0l[2] = {bl4[0], bl4[1]};
                uint32_t b1l[2] = {bl4[2], bl4[3]};
#pragma unroll
                for (int fm = 0; fm < 4; fm++) {
                    float* a0 = acc[fm][nb * 2];
                    float* a1 = acc[fm][nb * 2 + 1];
                    mma16816(a0, ah[fm], b0h);
                    mma16816(a1, ah[fm], b1h);
                    mma16816(a0, ah[fm], b0l);
                    mma16816(a1, ah[fm], b1l);
                    mma16816(a0, al[fm], b0h);
                    mma16816(a1, al[fm], b1h);
                }
            }
        }

        __syncthreads();

        if (i + 2 < NCHUNK)
            g_load_stage(sb + (uint32_t)(i & 1) * STAGE_B, A, B, m0, n0, (i + 2) * 64, tid);
    }

    // epilogue
    const int erow = lane >> 2;
    const int ecol = (lane & 3) * 2;
#pragma unroll
    for (int fm = 0; fm < 4; fm++) {
#pragma unroll
        for (int fn = 0; fn < 8; fn++) {
            int gm = m0 + warp_m + fm * 16 + erow;
            int gn = n0 + warp_n + fn * 8 + ecol;
            float2 v0 = make_float2(acc[fm][fn][0], acc[fm][fn][1]);
            float2 v1 = make_float2(acc[fm][fn][2], acc[fm][fn][3]);
            if (bias) {
                float2 bv = *(const float2*)(bias + gn);
                v0.x += bv.x; v0.y += bv.y;
                v1.x += bv.x; v1.y += bv.y;
            }
            *(float2*)(C + (size_t)gm * GN + gn) = v0;
            *(float2*)(C + (size_t)(gm + 8) * GN + gn) = v1;
        }
    }
}

// ---------------------------------------------------------------------------
// fp32 -> [hi | lo] bf16 split kernels
// ---------------------------------------------------------------------------
union BF4 { __nv_bfloat16 b[4]; uint2 u; };

__device__ __forceinline__ void split4(float4 v, uint2& h, uint2& l) {
    BF4 H, L;
    float f[4] = {v.x, v.y, v.z, v.w};
#pragma unroll
    for (int j = 0; j < 4; j++) {
        __nv_bfloat16 hb = __float2bfloat16(f[j]);
        H.b[j] = hb;
        L.b[j] = __float2bfloat16(f[j] - __bfloat162float(hb));
    }
    h = H.u; l = L.u;
}

__global__ void split_plain(const float4* __restrict__ x, uint2* __restrict__ o, int n4)
{
    int i = blockIdx.x * blockDim.x + threadIdx.x;
    if (i >= n4) return;
    uint2 h, l;
    split4(x[i], h, l);
    size_t ob = (size_t)(i >> 8) * 512 + (i & 255);
    o[ob] = h; o[ob + 256] = l;
}

__global__ void split_mask(const float4* __restrict__ x, const float4* __restrict__ m,
                           uint2* __restrict__ o, int n4)
{
    int i = blockIdx.x * blockDim.x + threadIdx.x;
    if (i >= n4) return;
    float4 v = x[i], mk = m[i];
    v.x *= mk.x; v.y *= mk.y; v.z *= mk.z; v.w *= mk.w;
    uint2 h, l;
    split4(v, h, l);
    size_t ob = (size_t)(i >> 8) * 512 + (i & 255);
    o[ob] = h; o[ob + 256] = l;
}

// ---------------------------------------------------------------------------
// HMMA local attention with online softmax (flash-style, bf16x3 split).
// (unchanged from R7 — verified correct, rel_err 2.7e-5)
// ---------------------------------------------------------------------------
#define ATT_SMEM 49152

__device__ __forceinline__ void cvt_load64(const float* __restrict__ src,
                                           uint32_t dh, uint32_t dl, int tid)
{
    int r = tid >> 1, half = tid & 1;
    const float* p = src + (size_t)r * CH + half * 32;
#pragma unroll
    for (int c4 = 0; c4 < 4; c4++) {
        float4 v0 = *(const float4*)(p + c4 * 8);
        float4 v1 = *(const float4*)(p + c4 * 8 + 4);
        uint32_t h0, L0, h1, L1, h2, L2, h3, L3;
        split_pack2(v0.x, v0.y, h0, L0);
        split_pack2(v0.z, v0.w, h1, L1);
        split_pack2(v1.x, v1.y, h2, L2);
        split_pack2(v1.z, v1.w, h3, L3);
        int chunk = half * 4 + c4;
        uint32_t off = (uint32_t)(r * 128) + (uint32_t)(((chunk ^ (r & 7)) << 4));
        asm volatile("st.shared.v4.b32 [%0], {%1,%2,%3,%4};"
                     :: "r"(dh + off), "r"(h0), "r"(h1), "r"(h2), "r"(h3) : "memory");
        asm volatile("st.shared.v4.b32 [%0], {%1,%2,%3,%4};"
                     :: "r"(dl + off), "r"(L0), "r"(L1), "r"(L2), "r"(L3) : "memory");
    }
}

__global__ void __launch_bounds__(128, 3) attn_hmma_kernel()
{
    const uint32_t sb = smem_u32(dsmem);
    const uint32_t sQh = sb,          sQl = sb + 8192;
    const uint32_t sKh = sb + 16384,  sKl = sb + 24576;
    const uint32_t sVh = sb + 32768,  sVl = sb + 40960;

    const int tid  = threadIdx.x;
    const int lane = tid & 31;
    const int wq   = tid >> 5;
    const int qbase = blockIdx.x * 64;
    const int head  = blockIdx.y;
    const int bb    = blockIdx.z;
    const size_t base = (size_t)bb * CS * CH + (size_t)head * CHD;

    const int idx = lane >> 3;
    const int lo7 = lane & 7;

    cvt_load64(g_Q + base + (size_t)qbase * CH, sQh, sQl, tid);
    __syncthreads();

    uint32_t qh[4][4], ql[4][4];
    {
        int q = wq * 16 + (idx & 1) * 8 + lo7;
#pragma unroll
        for (int ki = 0; ki < 4; ki++) {
            int ch = 2 * ki + (idx >> 1);
            ldsm4(qh[ki], tile_addr(sQh, q, ch));
            ldsm4(ql[ki], tile_addr(sQl, q, ch));
        }
    }

    float O[8][4];
#pragma unroll
    for (int f = 0; f < 8; f++)
#pragma unroll
        for (int c = 0; c < 4; c++) O[f][c] = 0.f;
    float m0 = -1e30f, m1 = -1e30f, l0 = 0.f, l1 = 0.f;

    const int i0 = qbase + wq * 16 + (lane >> 2);
    const int i1 = i0 + 8;

    for (int kb = 0; kb < 5; kb++) {
        int kbase = qbase - CWIN + kb * 64;
        if (kbase < 0) continue;
        __syncthreads();
        cvt_load64(g_K + base + (size_t)kbase * CH, sKh, sKl, tid);
        cvt_load64(g_V + base + (size_t)kbase * CH, sVh, sVl, tid);
        __syncthreads();

        float SF[8][4];
#pragma unroll
        for (int f = 0; f < 8; f++)
#pragma unroll
            for (int c = 0; c < 4; c++) SF[f][c] = 0.f;

#pragma unroll
        for (int ki = 0; ki < 4; ki++) {
#pragma unroll
            for (int tg = 0; tg < 4; tg++) {
                int t = tg * 16 + (idx & 1) * 8 + lo7;
                int ch = 2 * ki + (idx >> 1);
                uint32_t kh4[4], kl4[4];
                ldsm4(kh4, tile_addr(sKh, t, ch));
                ldsm4(kl4, tile_addr(sKl, t, ch));
                uint32_t b0[2] = {kh4[0], kh4[2]};
                uint32_t b1[2] = {kh4[1], kh4[3]};
                uint32_t c0[2] = {kl4[0], kl4[2]};
                uint32_t c1[2] = {kl4[1], kl4[3]};
                mma16816(SF[tg * 2],     qh[ki], b0);
                mma16816(SF[tg * 2 + 1], qh[ki], b1);
                mma16816(SF[tg * 2],     qh[ki], c0);
                mma16816(SF[tg * 2 + 1], qh[ki], c1);
                mma16816(SF[tg * 2],     ql[ki], b0);
                mma16816(SF[tg * 2 + 1], ql[ki], b1);
            }
        }

        float mx0 = -1e30f, mx1 = -1e30f;
#pragma unroll
        for (int f = 0; f < 8; f++) {
            int j0 = kbase + f * 8 + 2 * (lane & 3);
            int j1 = j0 + 1;
            if (!(j0 <= i0 && j0 > i0 - CWIN)) SF[f][0] = -1e30f;
            if (!(j1 <= i0 && j1 > i0 - CWIN)) SF[f][1] = -1e30f;
            if (!(j0 <= i1 && j0 > i1 - CWIN)) SF[f][2] = -1e30f;
            if (!(j1 <= i1 && j1 > i1 - CWIN)) SF[f][3] = -1e30f;
            mx0 = fmaxf(mx0, fmaxf(SF[f][0], SF[f][1]));
            mx1 = fmaxf(mx1, fmaxf(SF[f][2], SF[f][3]));
        }
        mx0 = fmaxf(mx0, __shfl_xor_sync(0xFFFFFFFFu, mx0, 1));
        mx0 = fmaxf(mx0, __shfl_xor_sync(0xFFFFFFFFu, mx0, 2));
        mx1 = fmaxf(mx1, __shfl_xor_sync(0xFFFFFFFFu, mx1, 1));
        mx1 = fmaxf(mx1, __shfl_xor_sync(0xFFFFFFFFu, mx1, 2));

        float mn0 = fmaxf(fmaxf(m0, mx0), -1e20f);
        float mn1 = fmaxf(fmaxf(m1, mx1), -1e20f);
        float sc0 = __expf(m0 - mn0);
        float sc1 = __expf(m1 - mn1);

        float s0 = 0.f, s1 = 0.f;
#pragma unroll
        for (int f = 0; f < 8; f++) {
            SF[f][0] = __expf(SF[f][0] - mn0);
            SF[f][1] = __expf(SF[f][1] - mn0);
            SF[f][2] = __expf(SF[f][2] - mn1);
            SF[f][3] = __expf(SF[f][3] - mn1);
            s0 += SF[f][0] + SF[f][1];
            s1 += SF[f][2] + SF[f][3];
        }
        s0 += __shfl_xor_sync(0xFFFFFFFFu, s0, 1);
        s0 += __shfl_xor_sync(0xFFFFFFFFu, s0, 2);
        s1 += __shfl_xor_sync(0xFFFFFFFFu, s1, 1);
        s1 += __shfl_xor_sync(0xFFFFFFFFu, s1, 2);
        l0 = l0 * sc0 + s0;
        l1 = l1 * sc1 + s1;
        m0 = mn0; m1 = mn1;

#pragma unroll
        for (int f = 0; f < 8; f++) {
            O[f][0] *= sc0; O[f][1] *= sc0;
            O[f][2] *= sc1; O[f][3] *= sc1;
        }

#pragma unroll
        for (int kt = 0; kt < 4; kt++) {
            uint32_t pah[4], pal[4];
            split_pack2(SF[2 * kt][0],     SF[2 * kt][1],     pah[0], pal[0]);
            split_pack2(SF[2 * kt][2],     SF[2 * kt][3],     pah[1], pal[1]);
            split_pack2(SF[2 * kt + 1][0], SF[2 * kt + 1][1], pah[2], pal[2]);
            split_pack2(SF[2 * kt + 1][2], SF[2 * kt + 1][3], pah[3], pal[3]);
#pragma unroll
            for (int dg = 0; dg < 4; dg++) {
                int t = kt * 16 + (idx & 1) * 8 + lo7;
                int ch = 2 * dg + (idx >> 1);
                uint32_t vh4[4], vl4[4];
                ldsm4t(vh4, tile_addr(sVh, t, ch));
                ldsm4t(vl4, tile_addr(sVl, t, ch));
                uint32_t b0h[2] = {vh4[0], vh4[1]};
                uint32_t b1h[2] = {vh4[2], vh4[3]};
                uint32_t b0l[2] = {vl4[0], vl4[1]};
                uint32_t b1l[2] = {vl4[2], vl4[3]};
                mma16816(O[2 * dg],     pah, b0h);
                mma16816(O[2 * dg + 1], pah, b1h);
                mma16816(O[2 * dg],     pah, b0l);
                mma16816(O[2 * dg + 1], pah, b1l);
                mma16816(O[2 * dg],     pal, b0h);
                mma16816(O[2 * dg + 1], pal, b1h);
            }
        }
    }

    float inv0 = 1.0f / l0;
    float inv1 = 1.0f / l1;
#pragma unroll
    for (int f = 0; f < 8; f++) {
        int col = f * 8 + 2 * (lane & 3);
        float2 v0 = make_float2(O[f][0] * inv0, O[f][1] * inv0);
        float2 v1 = make_float2(O[f][2] * inv1, O[f][3] * inv1);
        *(float2*)(g_ctx + base + (size_t)i0 * CH + col) = v0;
        *(float2*)(g_ctx + base + (size_t)i1 * CH + col) = v1;
    }
}

// ---------------------------------------------------------------------------
// kernel_launch
// ---------------------------------------------------------------------------
extern "C" void kernel_launch(void* const* d_in, const int* in_sizes, int n_in,
                              void* d_out, int out_size)
{
    const float* x   = (const float*)d_in[0];
    const float* xc  = (const float*)d_in[1];
    const float* abl = (const float*)d_in[2];
    const float* Wq  = (const float*)d_in[3];
    const float* Wk  = (const float*)d_in[4];
    const float* Wv  = (const float*)d_in[5];
    const float* Wo  = (const float*)d_in[6];
    const float* bo  = (const float*)d_in[7];
    float* out = (float*)d_out;

    float *qp, *kp, *vp, *cp;
    cudaGetSymbolAddress((void**)&qp, g_Q);
    cudaGetSymbolAddress((void**)&kp, g_K);
    cudaGetSymbolAddress((void**)&vp, g_V);
    cudaGetSymbolAddress((void**)&cp, g_ctx);
    __nv_bfloat16 *ax, *axc, *ac, *bq, *bk, *bv, *bo2;
    cudaGetSymbolAddress((void**)&ax,  g_Ax);
    cudaGetSymbolAddress((void**)&axc, g_Axc);
    cudaGetSymbolAddress((void**)&ac,  g_Ac);
    cudaGetSymbolAddress((void**)&bq,  g_Bq);
    cudaGetSymbolAddress((void**)&bk,  g_Bk);
    cudaGetSymbolAddress((void**)&bv,  g_Bv);
    cudaGetSymbolAddress((void**)&bo2, g_Bo);

    const int nAct4 = GM * CH / 4;
    const int nW4   = CH * CH / 4;

    split_plain<<<(nAct4 + 255) / 256, 256>>>((const float4*)x,  (uint2*)ax,  nAct4);
    split_plain<<<(nAct4 + 255) / 256, 256>>>((const float4*)xc, (uint2*)axc, nAct4);
    split_plain<<<(nW4 + 255) / 256, 256>>>((const float4*)Wq, (uint2*)bq,  nW4);
    split_plain<<<(nW4 + 255) / 256, 256>>>((const float4*)Wk, (uint2*)bk,  nW4);
    split_plain<<<(nW4 + 255) / 256, 256>>>((const float4*)Wv, (uint2*)bv,  nW4);
    split_plain<<<(nW4 + 255) / 256, 256>>>((const float4*)Wo, (uint2*)bo2, nW4);

    cudaFuncSetAttribute(gemm_hmma, cudaFuncAttributeMaxDynamicSharedMemorySize, GEMM_SMEM);
    dim3 ggrid(GN / 256, GM / 128);  // (4, 64)

    gemm_hmma<<<ggrid, 256, GEMM_SMEM>>>(ax,  bq,  qp, nullptr);
    gemm_hmma<<<ggrid, 256, GEMM_SMEM>>>(axc, bk,  kp, nullptr);
    gemm_hmma<<<ggrid, 256, GEMM_SMEM>>>(axc, bv,  vp, nullptr);

    cudaFuncSetAttribute(attn_hmma_kernel, cudaFuncAttributeMaxDynamicSharedMemorySize, ATT_SMEM);
    attn_hmma_kernel<<<dim3(CS / 64, CNH, CB), 128, ATT_SMEM>>>();

    split_mask<<<(nAct4 + 255) / 256, 256>>>((const float4*)cp, (const float4*)abl,
                                             (uint2*)ac, nAct4);

    gemm_hmma<<<ggrid, 256, GEMM_SMEM>>>(ac, bo2, out, bo);
}

// round 11
// speedup vs baseline: 3.4584x; 1.0508x over previous
#include <cuda_runtime.h>
#include <cuda_bf16.h>
#include <cstdint>

// Problem constants
#define CB   4
#define CS   2048
#define CH   1024
#define CNH  16
#define CHD  64
#define CWIN 256

#define GM   (CB * CS)   // 8192
#define GN   CH          // 1024
#define GK   CH          // 1024

// ---------------------------------------------------------------------------
// Scratch (allocation-free rule: __device__ globals) — all bf16 hi/lo pairs
// ---------------------------------------------------------------------------
__device__ __nv_bfloat16 g_Xh[GM * CH],  g_Xl[GM * CH];    // split(x)
__device__ __nv_bfloat16 g_XCh[GM * CH], g_XCl[GM * CH];   // split(x_clean)
__device__ __nv_bfloat16 g_Wqh[GN * GK], g_Wql[GN * GK];
__device__ __nv_bfloat16 g_Wkh[GN * GK], g_Wkl[GN * GK];
__device__ __nv_bfloat16 g_Wvh[GN * GK], g_Wvl[GN * GK];
__device__ __nv_bfloat16 g_Woh[GN * GK], g_Wol[GN * GK];
__device__ __nv_bfloat16 g_Qh[GM * CH],  g_Ql[GM * CH];    // projection outputs (pre-split)
__device__ __nv_bfloat16 g_Kh[GM * CH],  g_Kl[GM * CH];
__device__ __nv_bfloat16 g_Vh[GM * CH],  g_Vl[GM * CH];
__device__ __nv_bfloat16 g_Ach[GM * CH], g_Acl[GM * CH];   // ctx * mask, split

extern __shared__ char dsmem[];

// ---------------------------------------------------------------------------
// Helpers
// ---------------------------------------------------------------------------
__device__ __forceinline__ uint32_t smem_u32(const void* p) {
    uint32_t a;
    asm("{ .reg .u64 t; cvta.to.shared.u64 t, %1; cvt.u32.u64 %0, t; }"
        : "=r"(a) : "l"(p));
    return a;
}

__device__ __forceinline__ void cp16(uint32_t dst, const void* src) {
    asm volatile("cp.async.cg.shared.global [%0], [%1], 16;" :: "r"(dst), "l"(src) : "memory");
}
#define CP_COMMIT() asm volatile("cp.async.commit_group;" ::: "memory")
#define CP_WAIT0()  asm volatile("cp.async.wait_group 0;" ::: "memory")
#define CP_WAIT1()  asm volatile("cp.async.wait_group 1;" ::: "memory")

__device__ __forceinline__ void ldsm4(uint32_t* r, uint32_t addr) {
    asm volatile("ldmatrix.sync.aligned.m8n8.x4.shared.b16 {%0,%1,%2,%3}, [%4];"
                 : "=r"(r[0]), "=r"(r[1]), "=r"(r[2]), "=r"(r[3]) : "r"(addr));
}

__device__ __forceinline__ void ldsm4t(uint32_t* r, uint32_t addr) {
    asm volatile("ldmatrix.sync.aligned.m8n8.x4.trans.shared.b16 {%0,%1,%2,%3}, [%4];"
                 : "=r"(r[0]), "=r"(r[1]), "=r"(r[2]), "=r"(r[3]) : "r"(addr));
}

__device__ __forceinline__ void mma16816(float* c, const uint32_t* a, const uint32_t* b) {
    asm volatile(
        "mma.sync.aligned.m16n8k16.row.col.f32.bf16.bf16.f32 "
        "{%0,%1,%2,%3}, {%4,%5,%6,%7}, {%8,%9}, {%0,%1,%2,%3};"
        : "+f"(c[0]), "+f"(c[1]), "+f"(c[2]), "+f"(c[3])
        : "r"(a[0]), "r"(a[1]), "r"(a[2]), "r"(a[3]), "r"(b[0]), "r"(b[1]));
}

__device__ __forceinline__ void split_pack2(float e0, float e1, uint32_t& h, uint32_t& l) {
    __nv_bfloat16 b0 = __float2bfloat16(e0), b1 = __float2bfloat16(e1);
    __nv_bfloat162 hb; hb.x = b0; hb.y = b1;
    h = *reinterpret_cast<uint32_t*>(&hb);
    float r0 = e0 - __bfloat162float(b0);
    float r1 = e1 - __bfloat162float(b1);
    __nv_bfloat162 lb; lb.x = __float2bfloat16(r0); lb.y = __float2bfloat16(r1);
    l = *reinterpret_cast<uint32_t*>(&lb);
}

// smem tile address: row r, 16B chunk c (0..7), 128B rows, swizzled
__device__ __forceinline__ uint32_t tile_addr(uint32_t base, int r, int c) {
    return base + (uint32_t)(r * 128) + (uint32_t)(((c ^ (r & 7)) << 4));
}

// ---------------------------------------------------------------------------
// Persistent bf16x3 HMMA GEMM:
//   C = Ah*Bh^T + Ah*Bl^T + Al*Bh^T   per 128x256 tile-job
// 8 warps (64x64 warp tiles), BK=64, 2-stage cp.async, SW128.
// SPLIT=true: epilogue splits fp32 acc into bf16 hi/lo arrays (for attention).
// SPLIT=false: fp32 + bias (final output).
// ---------------------------------------------------------------------------
#define T_AH 0u
#define T_AL 16384u
#define T_BH 32768u
#define T_BL 65536u
#define STAGE_B 98304u            // 96 KB
#define GEMM_SMEM (2u * STAGE_B)  // 192 KB
#define NCHUNK 16                 // GK / 64

struct GParams {
    const __nv_bfloat16* Ah[3]; const __nv_bfloat16* Al[3];
    const __nv_bfloat16* Bh[3]; const __nv_bfloat16* Bl[3];
    __nv_bfloat16* Ch[3];       __nv_bfloat16* Cl[3];
    float* Cf; const float* bias;
    int njobs; int per_m;   // per_m = nproj * 4 n-tiles
};

__device__ __forceinline__ void g_load_stage(
    uint32_t st,
    const __nv_bfloat16* __restrict__ Ah, const __nv_bfloat16* __restrict__ Al,
    const __nv_bfloat16* __restrict__ Bh, const __nv_bfloat16* __restrict__ Bl,
    int m0, int n0, int kc, int tid)
{
#pragma unroll
    for (int t = 0; t < 4; t++) {          // A: 128 rows x 8 chunks (hi+lo)
        int id = tid + t * 256;
        int r = id >> 3, c = id & 7;
        uint32_t so = (uint32_t)(r * 128) + (uint32_t)(((c ^ (r & 7)) << 4));
        size_t off = (size_t)(m0 + r) * GK + kc + c * 8;
        cp16(st + T_AH + so, Ah + off);
        cp16(st + T_AL + so, Al + off);
    }
#pragma unroll
    for (int t = 0; t < 8; t++) {          // B: 256 rows x 8 chunks (hi+lo)
        int id = tid + t * 256;
        int r = id >> 3, c = id & 7;
        uint32_t so = (uint32_t)(r * 128) + (uint32_t)(((c ^ (r & 7)) << 4));
        size_t off = (size_t)(n0 + r) * GK + kc + c * 8;
        cp16(st + T_BH + so, Bh + off);
        cp16(st + T_BL + so, Bl + off);
    }
    CP_COMMIT();
}

template <bool SPLIT>
__global__ void __launch_bounds__(256, 1) gemm_persist(GParams P)
{
    const int tid  = threadIdx.x;
    const int wid  = tid >> 5;
    const int lane = tid & 31;
    const uint32_t sb = smem_u32(dsmem);

    const int warp_m = (wid & 1) * 64;
    const int warp_n = (wid >> 1) * 64;

    const int idx = lane >> 3;
    const int lo7 = lane & 7;
    const uint32_t xorv = (uint32_t)(lo7 * 16);
    const uint32_t rowA = (uint32_t)(warp_m + (idx & 1) * 8 + lo7);
    const uint32_t kA   = (uint32_t)((idx >> 1) * 16);
    const uint32_t rowB = (uint32_t)(warp_n + (idx >> 1) * 8 + lo7);
    const uint32_t kB   = (uint32_t)((idx & 1) * 16);

    const int erow = lane >> 2;
    const int ecol = (lane & 3) * 2;

    for (int job = blockIdx.x; job < P.njobs; job += gridDim.x) {
        int m_idx = job / P.per_m;
        int rem   = job - m_idx * P.per_m;
        int proj  = rem >> 2;
        int n_idx = rem & 3;
        int m0 = m_idx * 128, n0 = n_idx * 256;
        const __nv_bfloat16* Ah = P.Ah[proj];
        const __nv_bfloat16* Al = P.Al[proj];
        const __nv_bfloat16* Bh = P.Bh[proj];
        const __nv_bfloat16* Bl = P.Bl[proj];

        float acc[4][8][4];
#pragma unroll
        for (int i = 0; i < 4; i++)
#pragma unroll
            for (int j = 0; j < 8; j++)
#pragma unroll
                for (int q = 0; q < 4; q++) acc[i][j][q] = 0.f;

        g_load_stage(sb, Ah, Al, Bh, Bl, m0, n0, 0, tid);
        g_load_stage(sb + STAGE_B, Ah, Al, Bh, Bl, m0, n0, 64, tid);

        for (int i = 0; i < NCHUNK; i++) {
            if (i < NCHUNK - 1) { CP_WAIT1(); } else { CP_WAIT0(); }
            __syncthreads();

            uint32_t st = sb + (uint32_t)(i & 1) * STAGE_B;

#pragma unroll
            for (int ki = 0; ki < 4; ki++) {
                uint32_t koff = (uint32_t)(ki * 32);
                uint32_t ah[4][4], al[4][4];
#pragma unroll
                for (int fm = 0; fm < 4; fm++) {
                    uint32_t row = rowA + (uint32_t)(fm * 16);
                    uint32_t off = row * 128u + ((koff + kA) ^ xorv);
                    ldsm4(ah[fm], st + T_AH + off);
                    ldsm4(al[fm], st + T_AL + off);
                }
#pragma unroll
                for (int nb = 0; nb < 4; nb++) {
                    uint32_t row = rowB + (uint32_t)(nb * 16);
                    uint32_t off = row * 128u + ((koff + kB) ^ xorv);
                    uint32_t bh4[4], bl4[4];
                    ldsm4(bh4, st + T_BH + off);
                    ldsm4(bl4, st + T_BL + off);
                    uint32_t b0h[2] = {bh4[0], bh4[1]};
                    uint32_t b1h[2] = {bh4[2], bh4[3]};
                    uint32_t b0l[2] = {bl4[0], bl4[1]};
                    uint32_t b1l[2] = {bl4[2], bl4[3]};
#pragma unroll
                    for (int fm = 0; fm < 4; fm++) {
                        float* a0 = acc[fm][nb * 2];
                        float* a1 = acc[fm][nb * 2 + 1];
                        mma16816(a0, ah[fm], b0h);
                        mma16816(a1, ah[fm], b1h);
                        mma16816(a0, ah[fm], b0l);
                        mma16816(a1, ah[fm], b1l);
                        mma16816(a0, al[fm], b0h);
                        mma16816(a1, al[fm], b1h);
                    }
                }
            }

            __syncthreads();

            if (i + 2 < NCHUNK)
                g_load_stage(sb + (uint32_t)(i & 1) * STAGE_B, Ah, Al, Bh, Bl,
                             m0, n0, (i + 2) * 64, tid);
        }

        // epilogue
        if (SPLIT) {
            __nv_bfloat16* Ch = P.Ch[proj];
            __nv_bfloat16* Cl = P.Cl[proj];
#pragma unroll
            for (int fm = 0; fm < 4; fm++) {
#pragma unroll
                for (int fn = 0; fn < 8; fn++) {
                    int gm = m0 + warp_m + fm * 16 + erow;
                    int gn = n0 + warp_n + fn * 8 + ecol;
                    uint32_t h, l;
                    split_pack2(acc[fm][fn][0], acc[fm][fn][1], h, l);
                    *(uint32_t*)&Ch[(size_t)gm * GN + gn] = h;
                    *(uint32_t*)&Cl[(size_t)gm * GN + gn] = l;
                    split_pack2(acc[fm][fn][2], acc[fm][fn][3], h, l);
                    *(uint32_t*)&Ch[(size_t)(gm + 8) * GN + gn] = h;
                    *(uint32_t*)&Cl[(size_t)(gm + 8) * GN + gn] = l;
                }
            }
        } else {
            float* C = P.Cf;
            const float* bias = P.bias;
#pragma unroll
            for (int fm = 0; fm < 4; fm++) {
#pragma unroll
                for (int fn = 0; fn < 8; fn++) {
                    int gm = m0 + warp_m + fm * 16 + erow;
                    int gn = n0 + warp_n + fn * 8 + ecol;
                    float2 v0 = make_float2(acc[fm][fn][0], acc[fm][fn][1]);
                    float2 v1 = make_float2(acc[fm][fn][2], acc[fm][fn][3]);
                    if (bias) {
                        float2 bv = *(const float2*)(bias + gn);
                        v0.x += bv.x; v0.y += bv.y;
                        v1.x += bv.x; v1.y += bv.y;
                    }
                    *(float2*)(C + (size_t)gm * GN + gn) = v0;
                    *(float2*)(C + (size_t)(gm + 8) * GN + gn) = v1;
                }
            }
        }
    }
}

// ---------------------------------------------------------------------------
// fp32 -> separate hi/lo bf16 arrays
// ---------------------------------------------------------------------------
union BF4 { __nv_bfloat16 b[4]; uint2 u; };

__device__ __forceinline__ void split4(float4 v, uint2& h, uint2& l) {
    BF4 H, L;
    float f[4] = {v.x, v.y, v.z, v.w};
#pragma unroll
    for (int j = 0; j < 4; j++) {
        __nv_bfloat16 hb = __float2bfloat16(f[j]);
        H.b[j] = hb;
        L.b[j] = __float2bfloat16(f[j] - __bfloat162float(hb));
    }
    h = H.u; l = L.u;
}

__global__ void split2(const float4* __restrict__ x,
                       uint2* __restrict__ oh, uint2* __restrict__ ol, int n4)
{
    int i = blockIdx.x * blockDim.x + threadIdx.x;
    if (i >= n4) return;
    uint2 h, l;
    split4(x[i], h, l);
    oh[i] = h; ol[i] = l;
}

// ---------------------------------------------------------------------------
// HMMA local attention: pre-split bf16 Q/K/V, cp.async double-buffered K/V
// blocks, online softmax, epilogue fuses ablation mask + hi/lo split.
// 1 CTA = 64 queries x head x batch, 4 warps.
// ---------------------------------------------------------------------------
#define ATT_SMEM 81920   // Q 16K + 2 x 32K block buffers

// 64x64 bf16 tile (rows stride CH elems) -> swizzled smem, via cp.async
__device__ __forceinline__ void cp_tile64(const __nv_bfloat16* __restrict__ src,
                                          uint32_t dst, int tid)
{
#pragma unroll
    for (int t = 0; t < 4; t++) {
        int id = tid + t * 128;
        int r = id >> 3, c = id & 7;
        uint32_t off = (uint32_t)(r * 128) + (uint32_t)(((c ^ (r & 7)) << 4));
        cp16(dst + off, src + (size_t)r * CH + c * 8);
    }
}

__global__ void __launch_bounds__(128, 2) attn_hmma_kernel(const float* __restrict__ abl)
{
    const uint32_t sb  = smem_u32(dsmem);
    const uint32_t sQh = sb, sQl = sb + 8192;
    const uint32_t blk = sb + 16384;       // two 32 KB buffers

    const int tid  = threadIdx.x;
    const int lane = tid & 31;
    const int wq   = tid >> 5;
    const int qbase = blockIdx.x * 64;
    const int head  = blockIdx.y;
    const int bb    = blockIdx.z;
    const size_t base = (size_t)bb * CS * CH + (size_t)head * CHD;

    const int idx = lane >> 3;
    const int lo7 = lane & 7;

    int kb0 = 4 - (int)blockIdx.x; if (kb0 < 0) kb0 = 0;
    const int nblk = 5 - kb0;

    // prologue: Q + first block, one cp.async group
    cp_tile64(g_Qh + base + (size_t)qbase * CH, sQh, tid);
    cp_tile64(g_Ql + base + (size_t)qbase * CH, sQl, tid);
    {
        size_t ko = base + (size_t)(qbase - CWIN + kb0 * 64) * CH;
        cp_tile64(g_Kh + ko, blk,         tid);
        cp_tile64(g_Kl + ko, blk + 8192,  tid);
        cp_tile64(g_Vh + ko, blk + 16384, tid);
        cp_tile64(g_Vl + ko, blk + 24576, tid);
    }
    CP_COMMIT();

    uint32_t qh[4][4], ql[4][4];
    float O[8][4];
#pragma unroll
    for (int f = 0; f < 8; f++)
#pragma unroll
        for (int c = 0; c < 4; c++) O[f][c] = 0.f;
    float m0 = -1e30f, m1 = -1e30f, l0 = 0.f, l1 = 0.f;

    const int i0 = qbase + wq * 16 + (lane >> 2);
    const int i1 = i0 + 8;

    int buf = 0;
    for (int ib = 0; ib < nblk; ib++) {
        int kb = kb0 + ib;
        int kbase = qbase - CWIN + kb * 64;

        if (ib + 1 < nblk) {   // prefetch next block into other buffer
            uint32_t d = blk + (uint32_t)((buf ^ 1) * 32768);
            size_t ko = base + (size_t)(kbase + 64) * CH;
            cp_tile64(g_Kh + ko, d,         tid);
            cp_tile64(g_Kl + ko, d + 8192,  tid);
            cp_tile64(g_Vh + ko, d + 16384, tid);
            cp_tile64(g_Vl + ko, d + 24576, tid);
            CP_COMMIT();
            CP_WAIT1();        // current block's group complete
        } else {
            CP_WAIT0();
        }
        __syncthreads();

        if (ib == 0) {         // Q fragments (data arrived with first group)
            int q = wq * 16 + (idx & 1) * 8 + lo7;
#pragma unroll
            for (int ki = 0; ki < 4; ki++) {
                int ch = 2 * ki + (idx >> 1);
                ldsm4(qh[ki], tile_addr(sQh, q, ch));
                ldsm4(ql[ki], tile_addr(sQl, q, ch));
            }
        }

        const uint32_t sKh = blk + (uint32_t)(buf * 32768);
        const uint32_t sKl = sKh + 8192;
        const uint32_t sVh = sKh + 16384;
        const uint32_t sVl = sKh + 24576;

        // ---- S = Q K^T ----
        float SF[8][4];
#pragma unroll
        for (int f = 0; f < 8; f++)
#pragma unroll
            for (int c = 0; c < 4; c++) SF[f][c] = 0.f;

#pragma unroll
        for (int ki = 0; ki < 4; ki++) {
#pragma unroll
            for (int tg = 0; tg < 4; tg++) {
                int t = tg * 16 + (idx & 1) * 8 + lo7;
                int ch = 2 * ki + (idx >> 1);
                uint32_t kh4[4], kl4[4];
                ldsm4(kh4, tile_addr(sKh, t, ch));
                ldsm4(kl4, tile_addr(sKl, t, ch));
                uint32_t b0[2] = {kh4[0], kh4[2]};
                uint32_t b1[2] = {kh4[1], kh4[3]};
                uint32_t c0[2] = {kl4[0], kl4[2]};
                uint32_t c1[2] = {kl4[1], kl4[3]};
                mma16816(SF[tg * 2],     qh[ki], b0);
                mma16816(SF[tg * 2 + 1], qh[ki], b1);
                mma16816(SF[tg * 2],     qh[ki], c0);
                mma16816(SF[tg * 2 + 1], qh[ki], c1);
                mma16816(SF[tg * 2],     ql[ki], b0);
                mma16816(SF[tg * 2 + 1], ql[ki], b1);
            }
        }

        // ---- mask + online softmax ----
        float mx0 = -1e30f, mx1 = -1e30f;
#pragma unroll
        for (int f = 0; f < 8; f++) {
            int j0 = kbase + f * 8 + 2 * (lane & 3);
            int j1 = j0 + 1;
            if (!(j0 <= i0 && j0 > i0 - CWIN)) SF[f][0] = -1e30f;
            if (!(j1 <= i0 && j1 > i0 - CWIN)) SF[f][1] = -1e30f;
            if (!(j0 <= i1 && j0 > i1 - CWIN)) SF[f][2] = -1e30f;
            if (!(j1 <= i1 && j1 > i1 - CWIN)) SF[f][3] = -1e30f;
            mx0 = fmaxf(mx0, fmaxf(SF[f][0], SF[f][1]));
            mx1 = fmaxf(mx1, fmaxf(SF[f][2], SF[f][3]));
        }
        mx0 = fmaxf(mx0, __shfl_xor_sync(0xFFFFFFFFu, mx0, 1));
        mx0 = fmaxf(mx0, __shfl_xor_sync(0xFFFFFFFFu, mx0, 2));
        mx1 = fmaxf(mx1, __shfl_xor_sync(0xFFFFFFFFu, mx1, 1));
        mx1 = fmaxf(mx1, __shfl_xor_sync(0xFFFFFFFFu, mx1, 2));

        float mn0 = fmaxf(fmaxf(m0, mx0), -1e20f);
        float mn1 = fmaxf(fmaxf(m1, mx1), -1e20f);
        float sc0 = __expf(m0 - mn0);
        float sc1 = __expf(m1 - mn1);

        float s0 = 0.f, s1 = 0.f;
#pragma unroll
        for (int f = 0; f < 8; f++) {
            SF[f][0] = __expf(SF[f][0] - mn0);
            SF[f][1] = __expf(SF[f][1] - mn0);
            SF[f][2] = __expf(SF[f][2] - mn1);
            SF[f][3] = __expf(SF[f][3] - mn1);
            s0 += SF[f][0] + SF[f][1];
            s1 += SF[f][2] + SF[f][3];
        }
        s0 += __shfl_xor_sync(0xFFFFFFFFu, s0, 1);
        s0 += __shfl_xor_sync(0xFFFFFFFFu, s0, 2);
        s1 += __shfl_xor_sync(0xFFFFFFFFu, s1, 1);
        s1 += __shfl_xor_sync(0xFFFFFFFFu, s1, 2);
        l0 = l0 * sc0 + s0;
        l1 = l1 * sc1 + s1;
        m0 = mn0; m1 = mn1;

#pragma unroll
        for (int f = 0; f < 8; f++) {
            O[f][0] *= sc0; O[f][1] *= sc0;
            O[f][2] *= sc1; O[f][3] *= sc1;
        }

        // ---- O += P V ----
#pragma unroll
        for (int kt = 0; kt < 4; kt++) {
            uint32_t pah[4], pal[4];
            split_pack2(SF[2 * kt][0],     SF[2 * kt][1],     pah[0], pal[0]);
            split_pack2(SF[2 * kt][2],     SF[2 * kt][3],     pah[1], pal[1]);
            split_pack2(SF[2 * kt + 1][0], SF[2 * kt + 1][1], pah[2], pal[2]);
            split_pack2(SF[2 * kt + 1][2], SF[2 * kt + 1][3], pah[3], pal[3]);
#pragma unroll
            for (int dg = 0; dg < 4; dg++) {
                int t = kt * 16 + (idx & 1) * 8 + lo7;
                int ch = 2 * dg + (idx >> 1);
                uint32_t vh4[4], vl4[4];
                ldsm4t(vh4, tile_addr(sVh, t, ch));
                ldsm4t(vl4, tile_addr(sVl, t, ch));
                uint32_t b0h[2] = {vh4[0], vh4[1]};
                uint32_t b1h[2] = {vh4[2], vh4[3]};
                uint32_t b0l[2] = {vl4[0], vl4[1]};
                uint32_t b1l[2] = {vl4[2], vl4[3]};
                mma16816(O[2 * dg],     pah, b0h);
                mma16816(O[2 * dg + 1], pah, b1h);
                mma16816(O[2 * dg],     pah, b0l);
                mma16816(O[2 * dg + 1], pah, b1l);
                mma16816(O[2 * dg],     pal, b0h);
                mma16816(O[2 * dg + 1], pal, b1h);
            }
        }

        __syncthreads();   // all warps done with buf before it is refilled
        buf ^= 1;
    }

    // ---- epilogue: normalize, apply ablation mask, split, store ----
    float inv0 = 1.0f / l0;
    float inv1 = 1.0f / l1;
#pragma unroll
    for (int f = 0; f < 8; f++) {
        int col = f * 8 + 2 * (lane & 3);
        size_t o0 = base + (size_t)i0 * CH + col;
        size_t o1 = base + (size_t)i1 * CH + col;
        float2 mk0 = *(const float2*)(abl + o0);
        float2 mk1 = *(const float2*)(abl + o1);
        float a0 = O[f][0] * inv0 * mk0.x;
        float a1 = O[f][1] * inv0 * mk0.y;
        float b0 = O[f][2] * inv1 * mk1.x;
        float b1 = O[f][3] * inv1 * mk1.y;
        uint32_t h, l;
        split_pack2(a0, a1, h, l);
        *(uint32_t*)&g_Ach[o0] = h;
        *(uint32_t*)&g_Acl[o0] = l;
        split_pack2(b0, b1, h, l);
        *(uint32_t*)&g_Ach[o1] = h;
        *(uint32_t*)&g_Acl[o1] = l;
    }
}

// ---------------------------------------------------------------------------
// kernel_launch
// ---------------------------------------------------------------------------
extern "C" void kernel_launch(void* const* d_in, const int* in_sizes, int n_in,
                              void* d_out, int out_size)
{
    const float* x   = (const float*)d_in[0];
    const float* xc  = (const float*)d_in[1];
    const float* abl = (const float*)d_in[2];
    const float* Wq  = (const float*)d_in[3];
    const float* Wk  = (const float*)d_in[4];
    const float* Wv  = (const float*)d_in[5];
    const float* Wo  = (const float*)d_in[6];
    const float* bo  = (const float*)d_in[7];
    float* out = (float*)d_out;

    __nv_bfloat16 *xh, *xl, *xch, *xcl;
    __nv_bfloat16 *wqh, *wql, *wkh, *wkl, *wvh, *wvl, *woh, *wol;
    __nv_bfloat16 *qh, *ql, *kh, *kl, *vh, *vl, *ach, *acl;
    cudaGetSymbolAddress((void**)&xh,  g_Xh);  cudaGetSymbolAddress((void**)&xl,  g_Xl);
    cudaGetSymbolAddress((void**)&xch, g_XCh); cudaGetSymbolAddress((void**)&xcl, g_XCl);
    cudaGetSymbolAddress((void**)&wqh, g_Wqh); cudaGetSymbolAddress((void**)&wql, g_Wql);
    cudaGetSymbolAddress((void**)&wkh, g_Wkh); cudaGetSymbolAddress((void**)&wkl, g_Wkl);
    cudaGetSymbolAddress((void**)&wvh, g_Wvh); cudaGetSymbolAddress((void**)&wvl, g_Wvl);
    cudaGetSymbolAddress((void**)&woh, g_Woh); cudaGetSymbolAddress((void**)&wol, g_Wol);
    cudaGetSymbolAddress((void**)&qh,  g_Qh);  cudaGetSymbolAddress((void**)&ql,  g_Ql);
    cudaGetSymbolAddress((void**)&kh,  g_Kh);  cudaGetSymbolAddress((void**)&kl,  g_Kl);
    cudaGetSymbolAddress((void**)&vh,  g_Vh);  cudaGetSymbolAddress((void**)&vl,  g_Vl);
    cudaGetSymbolAddress((void**)&ach, g_Ach); cudaGetSymbolAddress((void**)&acl, g_Acl);

    const int nAct4 = GM * CH / 4;
    const int nW4   = GN * GK / 4;

    split2<<<(nAct4 + 255) / 256, 256>>>((const float4*)x,  (uint2*)xh,  (uint2*)xl,  nAct4);
    split2<<<(nAct4 + 255) / 256, 256>>>((const float4*)xc, (uint2*)xch, (uint2*)xcl, nAct4);
    split2<<<(nW4 + 255) / 256, 256>>>((const float4*)Wq, (uint2*)wqh, (uint2*)wql, nW4);
    split2<<<(nW4 + 255) / 256, 256>>>((const float4*)Wk, (uint2*)wkh, (uint2*)wkl, nW4);
    split2<<<(nW4 + 255) / 256, 256>>>((const float4*)Wv, (uint2*)wvh, (uint2*)wvl, nW4);
    split2<<<(nW4 + 255) / 256, 256>>>((const float4*)Wo, (uint2*)woh, (uint2*)wol, nW4);

    cudaFuncSetAttribute(gemm_persist<true>,  cudaFuncAttributeMaxDynamicSharedMemorySize, GEMM_SMEM);
    cudaFuncSetAttribute(gemm_persist<false>, cudaFuncAttributeMaxDynamicSharedMemorySize, GEMM_SMEM);
    cudaFuncSetAttribute(attn_hmma_kernel, cudaFuncAttributeMaxDynamicSharedMemorySize, ATT_SMEM);

    // QKV: one persistent launch, 768 jobs (64 m x 3 proj x 4 n)
    GParams Pq = {};
    Pq.Ah[0] = xh;  Pq.Al[0] = xl;   Pq.Bh[0] = wqh; Pq.Bl[0] = wql;
    Pq.Ah[1] = xch; Pq.Al[1] = xcl;  Pq.Bh[1] = wkh; Pq.Bl[1] = wkl;
    Pq.Ah[2] = xch; Pq.Al[2] = xcl;  Pq.Bh[2] = wvh; Pq.Bl[2] = wvl;
    Pq.Ch[0] = qh; Pq.Cl[0] = ql;
    Pq.Ch[1] = kh; Pq.Cl[1] = kl;
    Pq.Ch[2] = vh; Pq.Cl[2] = vl;
    Pq.njobs = 768; Pq.per_m = 12;
    gemm_persist<true><<<148, 256, GEMM_SMEM>>>(Pq);

    attn_hmma_kernel<<<dim3(CS / 64, CNH, CB), 128, ATT_SMEM>>>(abl);

    // Output GEMM: 256 jobs
    GParams Po = {};
    Po.Ah[0] = ach; Po.Al[0] = acl; Po.Bh[0] = woh; Po.Bl[0] = wol;
    Po.Cf = out; Po.bias = bo;
    Po.njobs = 256; Po.per_m = 4;
    gemm_persist<false><<<148, 256, GEMM_SMEM>>>(Po);
}